// round 11
// baseline (speedup 1.0000x reference)
#include <cuda_runtime.h>
#include <cuda_fp16.h>
#include <math.h>
#include <stdint.h>

// ---------------------------------------------------------------------------
// Problem dims (fixed by the dataset)
// ---------------------------------------------------------------------------
#define Bn 8
#define H 64
#define W 128
#define HW (H * W)            // 8192
#define C1CH 96               // tenOne / tenTwo channels
#define HIN 32
#define WIN 64
#define HWIN (HIN * WIN)      // 2048
#define PREVC 661

#define FEAT_C 629
#define FEAT_STRIDE (FEAT_C * HW)   // per-batch stride of feat

// channel offsets inside final feat (concats prepend):
// [c5(32) | c4(64) | c3(96) | c2(128) | c1(128) | vol(81) | tenOne(96) | flow(2) | upfeat(2)]
#define OFF_C5   0
#define OFF_C4   32
#define OFF_C3   96
#define OFF_C2   192
#define OFF_C1   320
#define OFF_VOL  448
#define OFF_T1   529
#define OFF_FLOW 625
#define OFF_UPF  627

// scratch: warped tenTwo
__device__ float g_warped[(size_t)Bn * C1CH * HW];

// packed (h,l) fp16 shadow of feat (u32 per pixel)
__device__ uint32_t g_half[(size_t)Bn * FEAT_C * HW];

// pre-packed fp16 (hi only) A-fragments, chunk = 144 k (16 channels x 9 taps)
// u32 per stage: nChunks*9*MFT*128
#define APACK_OFF1 0
#define APACK_OFF2 110592      // + 12*9*8*128
#define APACK_OFF3 294912      // + 20*9*8*128
#define APACK_OFF4 488448      // + 28*9*6*128
#define APACK_OFF5 645120      // + 34*9*4*128
#define APACK_TOTAL 732672     // + 38*9*2*128
__device__ uint32_t g_Apack[APACK_TOTAL];

// ---------------------------------------------------------------------------
// helpers
// ---------------------------------------------------------------------------
__device__ __forceinline__ uint32_t smem_u32(const void* p) {
    uint32_t a;
    asm("{ .reg .u64 t; cvta.to.shared.u64 t, %1; cvt.u32.u64 %0, t; }" : "=r"(a) : "l"(p));
    return a;
}
__device__ __forceinline__ void cp_async16(uint32_t dst, const void* src) {
    asm volatile("cp.async.ca.shared.global [%0], [%1], 16;" :: "r"(dst), "l"(src));
}
#define CP_COMMIT() asm volatile("cp.async.commit_group;")
#define CP_WAIT0()  asm volatile("cp.async.wait_group 0;")
#define CP_WAIT1()  asm volatile("cp.async.wait_group 1;")

__device__ __forceinline__ uint32_t packhl(float v) {
    __half h = __float2half_rn(v);
    __half l = __float2half_rn(v - __half2float(h));
    return (uint32_t)__half_as_ushort(h) | ((uint32_t)__half_as_ushort(l) << 16);
}

#define MMA_F16(c, a0, a1, a2, a3, b0v, b1v) \
    asm volatile( \
        "mma.sync.aligned.m16n8k16.row.col.f32.f16.f16.f32 " \
        "{%0,%1,%2,%3}, {%4,%5,%6,%7}, {%8,%9}, {%0,%1,%2,%3};" \
        : "+f"((c)[0]), "+f"((c)[1]), "+f"((c)[2]), "+f"((c)[3]) \
        : "r"(a0), "r"(a1), "r"(a2), "r"(a3), \
          "r"(b0v), "r"(b1v))

// ---------------------------------------------------------------------------
// Merged weight pre-pack (all 5 stages, one launch), hi fp16 only.
// u32 idx within a stage = (((kt*9+ks)*MFT + mf)*32 + lane)*4 + reg
//   m = mf*16 + (lane>>2) + 8*(reg&1)
//   k = kt*144 + ks*16 + (lane&3)*2 + 8*(reg>>1)   (pair k, k+1)
// ---------------------------------------------------------------------------
__device__ __forceinline__ void pack_one(const float* w, uint32_t* dst, int idx,
                                         int Cin, int Cout)
{
    int MFT = Cout >> 4;
    int reg = idx & 3, lane = (idx >> 2) & 31;
    int u = idx >> 7;
    int mf = u % MFT;
    int v3 = u / MFT;
    int ks = v3 % 9, kt = v3 / 9;
    int m = mf * 16 + (lane >> 2) + 8 * (reg & 1);
    int k = kt * 144 + ks * 16 + (lane & 3) * 2 + 8 * (reg >> 1);
    int K = Cin * 9;
    float v0 = (k     < K) ? w[(size_t)m * K + k]     : 0.f;
    float v1 = (k + 1 < K) ? w[(size_t)m * K + k + 1] : 0.f;
    __half h0 = __float2half_rn(v0), h1 = __float2half_rn(v1);
    dst[idx] = (uint32_t)__half_as_ushort(h0) | ((uint32_t)__half_as_ushort(h1) << 16);
}

__global__ void pack_all_kernel(const float* __restrict__ w1, const float* __restrict__ w2,
                                const float* __restrict__ w3, const float* __restrict__ w4,
                                const float* __restrict__ w5, uint32_t* __restrict__ dst)
{
    int idx = blockIdx.x * blockDim.x + threadIdx.x;
    if (idx >= APACK_TOTAL) return;
    if      (idx < APACK_OFF2) pack_one(w1, dst + APACK_OFF1, idx - APACK_OFF1, 181, 128);
    else if (idx < APACK_OFF3) pack_one(w2, dst + APACK_OFF2, idx - APACK_OFF2, 309, 128);
    else if (idx < APACK_OFF4) pack_one(w3, dst + APACK_OFF3, idx - APACK_OFF3, 437, 96);
    else if (idx < APACK_OFF5) pack_one(w4, dst + APACK_OFF4, idx - APACK_OFF4, 533, 64);
    else                       pack_one(w5, dst + APACK_OFF5, idx - APACK_OFF5, 597, 32);
}

// ---------------------------------------------------------------------------
// Merged ConvTranspose2d(k=4, s=2, p=1), Cout = 2; blockIdx.y selects which.
// Dual-writes fp32 feat + packed g_half.
// ---------------------------------------------------------------------------
__global__ void upconv_both_kernel(const float* __restrict__ inF, const float* __restrict__ wF,
                                   const float* __restrict__ bF,
                                   const float* __restrict__ inU, const float* __restrict__ wU,
                                   const float* __restrict__ bU,
                                   float* __restrict__ feat)
{
    int gid = blockIdx.x * blockDim.x + threadIdx.x;
    if (gid >= Bn * HW) return;
    const int which = blockIdx.y;
    const float* in  = which ? inU : inF;
    const float* w   = which ? wU  : wF;
    const float* bias= which ? bU  : bF;
    const int Cin    = which ? PREVC : 2;
    const int choff  = which ? OFF_UPF : OFF_FLOW;

    int b = gid / HW;
    int pix = gid - b * HW;
    int y = pix / W, x = pix - (pix / W) * W;

    int iy0 = y >> 1,                        ky0 = 1 + (y & 1);
    int iy1 = (y >> 1) + ((y & 1) ? 1 : -1), ky1 = (y & 1) ? 0 : 3;
    int ix0 = x >> 1,                        kx0 = 1 + (x & 1);
    int ix1 = (x >> 1) + ((x & 1) ? 1 : -1), kx1 = (x & 1) ? 0 : 3;
    bool vy1 = (unsigned)iy1 < HIN;
    bool vx1 = (unsigned)ix1 < WIN;

    float a0 = bias[0], a1 = bias[1];
    const float* pin = in + (size_t)b * Cin * HWIN;
    int w00i = ky0 * 4 + kx0, w01i = ky0 * 4 + kx1;
    int w10i = ky1 * 4 + kx0, w11i = ky1 * 4 + kx1;
    int p00 = iy0 * WIN + ix0, p01 = iy0 * WIN + ix1;
    int p10 = iy1 * WIN + ix0, p11 = iy1 * WIN + ix1;

    for (int ci = 0; ci < Cin; ci++) {
        const float* p = pin + (size_t)ci * HWIN;
        const float* wc = w + (size_t)ci * 32;
        float v = p[p00];
        a0 += v * wc[w00i];       a1 += v * wc[16 + w00i];
        if (vx1)        { float u = p[p01]; a0 += u * wc[w01i]; a1 += u * wc[16 + w01i]; }
        if (vy1)        { float u = p[p10]; a0 += u * wc[w10i]; a1 += u * wc[16 + w10i]; }
        if (vy1 && vx1) { float u = p[p11]; a0 += u * wc[w11i]; a1 += u * wc[16 + w11i]; }
    }
    size_t o = (size_t)b * FEAT_STRIDE + (size_t)choff * HW + pix;
    feat[o]      = a0;
    feat[o + HW] = a1;
    g_half[o]      = packhl(a0);
    g_half[o + HW] = packhl(a1);
}

// ---------------------------------------------------------------------------
// tenOne -> feat slice + packed shadow
// ---------------------------------------------------------------------------
__global__ void copy_t1_kernel(const float* __restrict__ t1, float* __restrict__ feat)
{
    size_t i = (size_t)blockIdx.x * blockDim.x + threadIdx.x;
    const size_t n4 = (size_t)Bn * C1CH * HW / 4;
    if (i >= n4) return;
    const size_t per = (size_t)C1CH * HW / 4;
    size_t b = i / per, r = i - b * per;
    float4 v = ((const float4*)t1)[i];
    size_t o = b * (size_t)FEAT_STRIDE + (size_t)OFF_T1 * HW;
    ((float4*)(feat + o))[r] = v;
    ((uint4*)(g_half + o))[r] = make_uint4(packhl(v.x), packhl(v.y), packhl(v.z), packhl(v.w));
}

__global__ void warp_kernel(const float* __restrict__ tenTwo, const float* __restrict__ feat)
{
    int gid = blockIdx.x * blockDim.x + threadIdx.x;
    if (gid >= Bn * HW) return;
    int b = gid / HW;
    int pix = gid - b * HW;
    int y = pix / W, x = pix - (pix / W) * W;

    const float* fl = feat + (size_t)b * FEAT_STRIDE + (size_t)OFF_FLOW * HW + pix;
    float px = (float)x + fl[0]  * 1.25f;
    float py = (float)y + fl[HW] * 1.25f;
    float fx = floorf(px), fy = floorf(py);
    float wx = px - fx, wy = py - fy;
    int ix0 = (int)fx, iy0 = (int)fy;
    int ix1 = ix0 + 1, iy1 = iy0 + 1;
    bool vx0 = (unsigned)ix0 < W, vx1 = (unsigned)ix1 < W;
    bool vy0 = (unsigned)iy0 < H, vy1 = (unsigned)iy1 < H;
    float w00 = (1.f - wy) * (1.f - wx), w01 = (1.f - wy) * wx;
    float w10 = wy * (1.f - wx),         w11 = wy * wx;
    int o00 = iy0 * W + ix0, o01 = iy0 * W + ix1;
    int o10 = iy1 * W + ix0, o11 = iy1 * W + ix1;

    const float* t = tenTwo + (size_t)b * C1CH * HW;
    float* o = g_warped + (size_t)b * C1CH * HW + pix;
    for (int c = 0; c < C1CH; c++) {
        const float* tc = t + (size_t)c * HW;
        float v = 0.f;
        if (vy0 && vx0) v += tc[o00] * w00;
        if (vy0 && vx1) v += tc[o01] * w01;
        if (vy1 && vx0) v += tc[o10] * w10;
        if (vy1 && vx1) v += tc[o11] * w11;
        o[(size_t)c * HW] = v;
    }
}

// correlation + leaky -> feat vol slice + packed shadow
__global__ __launch_bounds__(128) void corr_kernel(const float* __restrict__ tenOne,
                                                   float* __restrict__ feat)
{
    __shared__ float s_f1[4][32];
    __shared__ float s_w2[12][40];
    int tid = threadIdx.x;
    int tx = tid & 31, ty = tid >> 5;
    int x0 = blockIdx.x * 32, y0 = blockIdx.y * 4, b = blockIdx.z;

    float acc[81];
#pragma unroll
    for (int d = 0; d < 81; d++) acc[d] = 0.f;

    const float* f1 = tenOne + (size_t)b * C1CH * HW;
    const float* f2 = g_warped + (size_t)b * C1CH * HW;

    for (int c = 0; c < C1CH; c++) {
        const float* f1c = f1 + (size_t)c * HW;
        const float* f2c = f2 + (size_t)c * HW;
        __syncthreads();
        s_f1[ty][tx] = f1c[(y0 + ty) * W + x0 + tx];
#pragma unroll
        for (int i = 0; i < 4; i++) {
            int idx = tid + i * 128;
            if (idx < 480) {
                int r = idx / 40, cc = idx - (idx / 40) * 40;
                int gy = y0 - 4 + r, gx = x0 - 4 + cc;
                float v = 0.f;
                if ((unsigned)gy < H && (unsigned)gx < W) v = f2c[gy * W + gx];
                s_w2[r][cc] = v;
            }
        }
        __syncthreads();
        float a = s_f1[ty][tx];
#pragma unroll
        for (int dy = 0; dy < 9; dy++)
#pragma unroll
            for (int dx = 0; dx < 9; dx++)
                acc[dy * 9 + dx] += a * s_w2[ty + dy][tx + dx];
    }

    size_t obase = (size_t)b * FEAT_STRIDE + (size_t)OFF_VOL * HW + (y0 + ty) * W + x0 + tx;
    const float inv = 1.f / 96.f;
#pragma unroll
    for (int d = 0; d < 81; d++) {
        float v = acc[d] * inv;
        v = (v >= 0.f) ? v : 0.1f * v;
        feat[obase + (size_t)d * HW] = v;
        g_half[obase + (size_t)d * HW] = packhl(v);
    }
}

// ---------------------------------------------------------------------------
// FFMA direct 3x3 conv (kept for conv6, Cout=2)
// ---------------------------------------------------------------------------
template <int COUT_BLK>
__global__ __launch_bounds__(256) void conv3x3_kernel(
    const float* __restrict__ in, const float* __restrict__ w,
    const float* __restrict__ bias, float* __restrict__ out,
    int Cin, int inStride, int outStride)
{
    __shared__ float s_in[18][66];
    __shared__ float s_w[COUT_BLK * 9];
    const int tid = threadIdx.x;
    const int tx = tid & 15, ty = tid >> 4;
    const int g = blockIdx.x;
    const int tileX = blockIdx.y & 1, tileY = blockIdx.y >> 1;
    const int b = blockIdx.z;
    const int x0 = tileX * 64, y0 = tileY * 16;

    const float* inB = in + (size_t)b * inStride;
    float acc[COUT_BLK][4];
#pragma unroll
    for (int c = 0; c < COUT_BLK; c++)
#pragma unroll
        for (int p = 0; p < 4; p++) acc[c][p] = 0.f;

    for (int ci = 0; ci < Cin; ci++) {
        const float* ch = inB + (size_t)ci * HW;
#pragma unroll
        for (int i = 0; i < 5; i++) {
            int idx = tid + i * 256;
            if (idx < 18 * 66) {
                int r = idx / 66, c = idx - (idx / 66) * 66;
                int gy = y0 - 1 + r, gx = x0 - 1 + c;
                float v = 0.f;
                if ((unsigned)gy < H && (unsigned)gx < W) v = ch[gy * W + gx];
                s_in[r][c] = v;
            }
        }
        if (tid < COUT_BLK * 9)
            s_w[tid] = w[((size_t)(g * COUT_BLK + tid / 9) * Cin + ci) * 9 + tid % 9];
        __syncthreads();

        float r0[6], r1[6], r2[6];
#pragma unroll
        for (int k = 0; k < 6; k++) {
            r0[k] = s_in[ty][tx * 4 + k];
            r1[k] = s_in[ty + 1][tx * 4 + k];
            r2[k] = s_in[ty + 2][tx * 4 + k];
        }
#pragma unroll
        for (int co = 0; co < COUT_BLK; co++) {
            float w0 = s_w[co * 9 + 0], w1v = s_w[co * 9 + 1], w2v = s_w[co * 9 + 2];
            float w3v = s_w[co * 9 + 3], w4v = s_w[co * 9 + 4], w5v = s_w[co * 9 + 5];
            float w6v = s_w[co * 9 + 6], w7v = s_w[co * 9 + 7], w8v = s_w[co * 9 + 8];
#pragma unroll
            for (int p = 0; p < 4; p++) {
                float s = acc[co][p];
                s += w0  * r0[p]; s += w1v * r0[p + 1]; s += w2v * r0[p + 2];
                s += w3v * r1[p]; s += w4v * r1[p + 1]; s += w5v * r1[p + 2];
                s += w6v * r2[p]; s += w7v * r2[p + 1]; s += w8v * r2[p + 2];
                acc[co][p] = s;
            }
        }
        __syncthreads();
    }

#pragma unroll
    for (int co = 0; co < COUT_BLK; co++) {
        float bi = bias[g * COUT_BLK + co];
        float* o = out + (size_t)b * outStride + (size_t)(g * COUT_BLK + co) * HW
                 + (y0 + ty) * W + x0 + tx * 4;
#pragma unroll
        for (int p = 0; p < 4; p++) {
            float v = acc[co][p] + bi;
            o[p] = (v >= 0.f) ? v : 0.1f * v;
        }
    }
}

// ---------------------------------------------------------------------------
// Implicit-GEMM 3x3 conv via mma.sync m16n8k16 fp16, 2-term split:
//   D = w_h·x_h + w_h·x_l   (weight fp16-rounded; activation hi/lo split)
// Chunk = 144 k = 16 channels x 9 taps. Packed activation rows staged via
// cp.async (double-buffered). A (hi) fragments software-pipelined over ks.
// Warp tile 32(M) x 64(N). Epilogue dual-writes fp32 feat + packed g_half.
// ---------------------------------------------------------------------------
template <int Cin, int Cout, int NW, int NROWS, int THREADS, int MINB>
__global__ __launch_bounds__(THREADS, MINB) void conv_mma3_kernel(
    const uint32_t* __restrict__ inBase,
    const uint4* __restrict__ Apack,
    const float* __restrict__ bias,
    float* __restrict__ outBase,
    uint32_t* __restrict__ outHalfBase)
{
    constexpr int nC    = (Cin + 15) / 16;
    constexpr int R     = NROWS + 2;
    constexpr int SROW  = 136;
    constexpr int BUFSZ = 16 * R * SROW;
    constexpr int MFT   = Cout / 16;

    extern __shared__ uint32_t raw[];
    const int tid = threadIdx.x, lane = tid & 31, wrp = tid >> 5;
    const int wm = wrp / NW, wn = wrp % NW;
    const int wm0 = wm * 32, wn0 = wn * 64;
    const int wrow = wn0 >> 7, wcol = wn0 & 127;
    const int yBase = blockIdx.x * NROWS, b = blockIdx.y;
    const uint32_t* inB = inBase + (size_t)b * FEAT_STRIDE;
    const uint32_t rawAddr = smem_u32(raw);

    // warp-local A pointer (mf = wm*2 + mi); per-mf stride = 32 uint4
    const uint4* apw = Apack + (size_t)(wm * 2) * 32 + lane;

    for (int i = tid; i < 2 * 16 * R; i += THREADS) {
        raw[i * SROW + 3]   = 0u;
        raw[i * SROW + 132] = 0u;
    }

    float acc[2][8][4];
#pragma unroll
    for (int mi = 0; mi < 2; mi++)
#pragma unroll
        for (int ni = 0; ni < 8; ni++)
#pragma unroll
            for (int p = 0; p < 4; p++) acc[mi][ni][p] = 0.f;

    auto stage = [&](int kt, int bufsel) {
        const int total = 16 * R * 32;
        for (int i = tid; i < total; i += THREADS) {
            int c   = i / (R * 32);
            int rem = i - c * (R * 32);
            int rr  = rem >> 5, v = rem & 31;
            int ci  = kt * 16 + c;
            int gy  = yBase + rr - 1;
            int foff = bufsel * BUFSZ + (c * R + rr) * SROW + 4 + v * 4;
            if (ci < Cin && (unsigned)gy < (unsigned)H) {
                cp_async16(rawAddr + (uint32_t)(foff * 4),
                           inB + (size_t)ci * HW + gy * W + v * 4);
            } else {
                *(uint4*)(raw + foff) = make_uint4(0u, 0u, 0u, 0u);
            }
        }
    };

    stage(0, 0);
    CP_COMMIT();

    const int t = lane & 3;
    const int nbase = wcol + (lane >> 2);

    // A software pipeline: preload (kt=0, ks=0)
    uint4 ah0, ah1;
    {
        const uint4* p = apw;
        ah0 = p[0]; ah1 = p[32];
    }

    for (int kt = 0; kt < nC; kt++) {
        const int buf = kt & 1;
        if (kt + 1 < nC) {
            stage(kt + 1, buf ^ 1);
            CP_COMMIT();
            CP_WAIT1();
        } else {
            CP_WAIT0();
        }
        __syncthreads();

        const uint32_t* rb = raw + buf * BUFSZ;

#pragma unroll
        for (int ks = 0; ks < 9; ks++) {
            // prefetch next A fragment set (next ks, or next chunk's ks0)
            uint4 nh0, nh1;
            {
                int nkt = kt, nks = ks + 1;
                if (nks == 9) { nkt = kt + 1; nks = 0; }
                if (nkt < nC) {
                    const uint4* p = apw + (size_t)((nkt * 9 + nks) * MFT) * 32;
                    nh0 = p[0]; nh1 = p[32];
                } else {
                    nh0 = nh1 = make_uint4(0u, 0u, 0u, 0u);
                }
            }

            int j0 = ks * 16 + 2 * t, j1 = j0 + 8;
            const uint32_t* q0;
            const uint32_t* q1;
            const uint32_t* q2;
            const uint32_t* q3;
            {
                int c = j0 / 9, tp = j0 - c * 9;
                q0 = rb + (c * R + wrow + tp / 3) * SROW + (tp % 3) + 3 + nbase;
            }
            {
                int jj = j0 + 1;
                int c = jj / 9, tp = jj - c * 9;
                q1 = rb + (c * R + wrow + tp / 3) * SROW + (tp % 3) + 3 + nbase;
            }
            {
                int c = j1 / 9, tp = j1 - c * 9;
                q2 = rb + (c * R + wrow + tp / 3) * SROW + (tp % 3) + 3 + nbase;
            }
            {
                int jj = j1 + 1;
                int c = jj / 9, tp = jj - c * 9;
                q3 = rb + (c * R + wrow + tp / 3) * SROW + (tp % 3) + 3 + nbase;
            }

#pragma unroll
            for (int nf = 0; nf < 8; nf++) {
                uint32_t w00 = q0[nf * 8], w01 = q1[nf * 8];
                uint32_t w10 = q2[nf * 8], w11 = q3[nf * 8];
                uint32_t bh0 = __byte_perm(w00, w01, 0x5410);
                uint32_t bl0 = __byte_perm(w00, w01, 0x7632);
                uint32_t bh1 = __byte_perm(w10, w11, 0x5410);
                uint32_t bl1 = __byte_perm(w10, w11, 0x7632);
                MMA_F16(acc[0][nf], ah0.x, ah0.y, ah0.z, ah0.w, bh0, bh1);
                MMA_F16(acc[1][nf], ah1.x, ah1.y, ah1.z, ah1.w, bh0, bh1);
                MMA_F16(acc[0][nf], ah0.x, ah0.y, ah0.z, ah0.w, bl0, bl1);
                MMA_F16(acc[1][nf], ah1.x, ah1.y, ah1.z, ah1.w, bl0, bl1);
            }
            ah0 = nh0; ah1 = nh1;
        }
        __syncthreads();
    }

    // ---- epilogue: bias + leaky; dual-write fp32 feat + packed g_half ----
    const int q = lane & 3, g2 = lane >> 2;
    float* outB = outBase + (size_t)b * FEAT_STRIDE;
    uint32_t* outH = outHalfBase + (size_t)b * FEAT_STRIDE;
#pragma unroll
    for (int mi = 0; mi < 2; mi++) {
        int m0 = wm0 + mi * 16 + g2;
        float bLo = __ldg(bias + m0), bHi = __ldg(bias + m0 + 8);
        float* o0 = outB + (size_t)m0 * HW;
        float* o1 = o0 + 8 * HW;
        uint32_t* h0 = outH + (size_t)m0 * HW;
        uint32_t* h1 = h0 + 8 * HW;
#pragma unroll
        for (int ni = 0; ni < 8; ni++) {
            int n = wn0 + ni * 8 + 2 * q;
            int off = (yBase + (n >> 7)) * W + (n & 127);
            float v0 = acc[mi][ni][0] + bLo, v1 = acc[mi][ni][1] + bLo;
            float v2 = acc[mi][ni][2] + bHi, v3 = acc[mi][ni][3] + bHi;
            v0 = (v0 >= 0.f) ? v0 : 0.1f * v0;
            v1 = (v1 >= 0.f) ? v1 : 0.1f * v1;
            v2 = (v2 >= 0.f) ? v2 : 0.1f * v2;
            v3 = (v3 >= 0.f) ? v3 : 0.1f * v3;
            *(float2*)(o0 + off) = make_float2(v0, v1);
            *(float2*)(o1 + off) = make_float2(v2, v3);
            *(uint2*)(h0 + off) = make_uint2(packhl(v0), packhl(v1));
            *(uint2*)(h1 + off) = make_uint2(packhl(v2), packhl(v3));
        }
    }
}

// ---------------------------------------------------------------------------
// Launch
// ---------------------------------------------------------------------------
extern "C" void kernel_launch(void* const* d_in, const int* in_sizes, int n_in,
                              void* d_out, int out_size)
{
    (void)in_sizes; (void)n_in; (void)out_size;
    const float* tenOne    = (const float*)d_in[0];
    const float* tenTwo    = (const float*)d_in[1];
    const float* prev_flow = (const float*)d_in[2];
    const float* prev_feat = (const float*)d_in[3];
    const float* w_upflow  = (const float*)d_in[4];
    const float* b_upflow  = (const float*)d_in[5];
    const float* w_upfeat  = (const float*)d_in[6];
    const float* b_upfeat  = (const float*)d_in[7];
    const float* w1 = (const float*)d_in[8];   const float* b1 = (const float*)d_in[9];
    const float* w2 = (const float*)d_in[10];  const float* b2 = (const float*)d_in[11];
    const float* w3 = (const float*)d_in[12];  const float* b3 = (const float*)d_in[13];
    const float* w4 = (const float*)d_in[14];  const float* b4 = (const float*)d_in[15];
    const float* w5 = (const float*)d_in[16];  const float* b5 = (const float*)d_in[17];
    const float* w6 = (const float*)d_in[18];  const float* b6 = (const float*)d_in[19];

    float* flow = (float*)d_out;
    float* feat = flow + (size_t)Bn * 2 * HW;

    uint32_t* apack;
    cudaGetSymbolAddress((void**)&apack, g_Apack);
    uint32_t* half;
    cudaGetSymbolAddress((void**)&half, g_half);

    const int SMA = 52224, SMB = 69632;
    cudaFuncSetAttribute(conv_mma3_kernel<181, 128, 2, 1, 256, 2>, cudaFuncAttributeMaxDynamicSharedMemorySize, SMA);
    cudaFuncSetAttribute(conv_mma3_kernel<309, 128, 2, 1, 256, 2>, cudaFuncAttributeMaxDynamicSharedMemorySize, SMA);
    cudaFuncSetAttribute(conv_mma3_kernel<437,  96, 2, 1, 192, 2>, cudaFuncAttributeMaxDynamicSharedMemorySize, SMA);
    cudaFuncSetAttribute(conv_mma3_kernel<533,  64, 2, 1, 128, 3>, cudaFuncAttributeMaxDynamicSharedMemorySize, SMA);
    cudaFuncSetAttribute(conv_mma3_kernel<597,  32, 4, 2, 128, 3>, cudaFuncAttributeMaxDynamicSharedMemorySize, SMB);

    const int NPIX = Bn * HW;

    // 0. merged weight pre-pack
    pack_all_kernel<<<(APACK_TOTAL + 255) / 256, 256>>>(w1, w2, w3, w4, w5, apack);
    // 1. both upconvs (dual-write)
    upconv_both_kernel<<<dim3((NPIX + 255) / 256, 2), 256>>>(
        prev_flow, w_upflow, b_upflow, prev_feat, w_upfeat, b_upfeat, feat);
    // 2. tenOne (dual-write)
    {
        size_t n4 = (size_t)Bn * C1CH * HW / 4;
        copy_t1_kernel<<<(unsigned)((n4 + 255) / 256), 256>>>(tenOne, feat);
    }
    // 3. warp tenTwo
    warp_kernel<<<(NPIX + 255) / 256, 256>>>(tenTwo, feat);
    // 4. correlation (dual-write)
    corr_kernel<<<dim3(W / 32, H / 4, Bn), 128>>>(tenOne, feat);

    // 5-9. fp16 2-term mma conv tower
    conv_mma3_kernel<181, 128, 2, 1, 256, 2><<<dim3(64, Bn), 256, SMA>>>(
        half + (size_t)OFF_VOL * HW, (const uint4*)(apack + APACK_OFF1), b1,
        feat + (size_t)OFF_C1 * HW, half + (size_t)OFF_C1 * HW);
    conv_mma3_kernel<309, 128, 2, 1, 256, 2><<<dim3(64, Bn), 256, SMA>>>(
        half + (size_t)OFF_C1 * HW, (const uint4*)(apack + APACK_OFF2), b2,
        feat + (size_t)OFF_C2 * HW, half + (size_t)OFF_C2 * HW);
    conv_mma3_kernel<437, 96, 2, 1, 192, 2><<<dim3(64, Bn), 192, SMA>>>(
        half + (size_t)OFF_C2 * HW, (const uint4*)(apack + APACK_OFF3), b3,
        feat + (size_t)OFF_C3 * HW, half + (size_t)OFF_C3 * HW);
    conv_mma3_kernel<533, 64, 2, 1, 128, 3><<<dim3(64, Bn), 128, SMA>>>(
        half + (size_t)OFF_C3 * HW, (const uint4*)(apack + APACK_OFF4), b4,
        feat + (size_t)OFF_C4 * HW, half + (size_t)OFF_C4 * HW);
    conv_mma3_kernel<597, 32, 4, 2, 128, 3><<<dim3(32, Bn), 128, SMB>>>(
        half + (size_t)OFF_C4 * HW, (const uint4*)(apack + APACK_OFF5), b5,
        feat + (size_t)OFF_C5 * HW, half + (size_t)OFF_C5 * HW);

    // 10. conv6 (Cout=2) -> flow, FFMA path
    conv3x3_kernel<2><<<dim3(1, 8, Bn), 256>>>(
        feat + (size_t)OFF_C5 * HW, w6, b6, flow,
        629, FEAT_STRIDE, 2 * HW);
}

// round 12
// speedup vs baseline: 1.4188x; 1.4188x over previous
#include <cuda_runtime.h>
#include <cuda_fp16.h>
#include <math.h>
#include <stdint.h>

// ---------------------------------------------------------------------------
// Problem dims (fixed by the dataset)
// ---------------------------------------------------------------------------
#define Bn 8
#define H 64
#define W 128
#define HW (H * W)            // 8192
#define C1CH 96
#define HIN 32
#define WIN 64
#define HWIN (HIN * WIN)
#define PREVC 661

#define FEAT_C 629
#define FEAT_STRIDE (FEAT_C * HW)

// [c5(32) | c4(64) | c3(96) | c2(128) | c1(128) | vol(81) | tenOne(96) | flow(2) | upfeat(2)]
#define OFF_C5   0
#define OFF_C4   32
#define OFF_C3   96
#define OFF_C2   192
#define OFF_C1   320
#define OFF_VOL  448
#define OFF_T1   529
#define OFF_FLOW 625
#define OFF_UPF  627

__device__ float g_warped[(size_t)Bn * C1CH * HW];

// packed (h,l) fp16 shadow of feat (u32 per pixel)
__device__ uint32_t g_half[(size_t)Bn * FEAT_C * HW];

// pre-packed fp16 (hi only) A-fragments, chunk = 144 k (16 channels x 9 taps)
#define APACK_OFF1 0
#define APACK_OFF2 110592      // + 12*9*8*128
#define APACK_OFF3 294912      // + 20*9*8*128
#define APACK_OFF4 488448      // + 28*9*6*128
#define APACK_OFF5 645120      // + 34*9*4*128
#define APACK_TOTAL 732672     // + 38*9*2*128
__device__ uint32_t g_Apack[APACK_TOTAL];

// ---------------------------------------------------------------------------
// helpers
// ---------------------------------------------------------------------------
__device__ __forceinline__ uint32_t smem_u32(const void* p) {
    uint32_t a;
    asm("{ .reg .u64 t; cvta.to.shared.u64 t, %1; cvt.u32.u64 %0, t; }" : "=r"(a) : "l"(p));
    return a;
}
__device__ __forceinline__ void cp_async16(uint32_t dst, const void* src) {
    asm volatile("cp.async.ca.shared.global [%0], [%1], 16;" :: "r"(dst), "l"(src));
}
__device__ __forceinline__ void cp_async4(uint32_t dst, const void* src) {
    asm volatile("cp.async.ca.shared.global [%0], [%1], 4;" :: "r"(dst), "l"(src));
}
#define CP_COMMIT() asm volatile("cp.async.commit_group;")
#define CP_WAIT0()  asm volatile("cp.async.wait_group 0;")
#define CP_WAIT1()  asm volatile("cp.async.wait_group 1;")

__device__ __forceinline__ uint32_t packhl(float v) {
    __half h = __float2half_rn(v);
    __half l = __float2half_rn(v - __half2float(h));
    return (uint32_t)__half_as_ushort(h) | ((uint32_t)__half_as_ushort(l) << 16);
}

#define MMA_F16(c, a0, a1, a2, a3, b0v, b1v) \
    asm volatile( \
        "mma.sync.aligned.m16n8k16.row.col.f32.f16.f16.f32 " \
        "{%0,%1,%2,%3}, {%4,%5,%6,%7}, {%8,%9}, {%0,%1,%2,%3};" \
        : "+f"((c)[0]), "+f"((c)[1]), "+f"((c)[2]), "+f"((c)[3]) \
        : "r"(a0), "r"(a1), "r"(a2), "r"(a3), \
          "r"(b0v), "r"(b1v))

// ---------------------------------------------------------------------------
// Merged weight pre-pack (all 5 stages, one launch), hi fp16 only.
// u32 idx within a stage = (((kt*9+ks)*MFT + mf)*32 + lane)*4 + reg
//   m = mf*16 + (lane>>2) + 8*(reg&1)
//   k = kt*144 + ks*16 + (lane&3)*2 + 8*(reg>>1)   (pair k, k+1)
// ---------------------------------------------------------------------------
__device__ __forceinline__ void pack_one(const float* w, uint32_t* dst, int idx,
                                         int Cin, int Cout)
{
    int MFT = Cout >> 4;
    int reg = idx & 3, lane = (idx >> 2) & 31;
    int u = idx >> 7;
    int mf = u % MFT;
    int v3 = u / MFT;
    int ks = v3 % 9, kt = v3 / 9;
    int m = mf * 16 + (lane >> 2) + 8 * (reg & 1);
    int k = kt * 144 + ks * 16 + (lane & 3) * 2 + 8 * (reg >> 1);
    int K = Cin * 9;
    float v0 = (k     < K) ? w[(size_t)m * K + k]     : 0.f;
    float v1 = (k + 1 < K) ? w[(size_t)m * K + k + 1] : 0.f;
    __half h0 = __float2half_rn(v0), h1 = __float2half_rn(v1);
    dst[idx] = (uint32_t)__half_as_ushort(h0) | ((uint32_t)__half_as_ushort(h1) << 16);
}

__global__ void pack_all_kernel(const float* __restrict__ w1, const float* __restrict__ w2,
                                const float* __restrict__ w3, const float* __restrict__ w4,
                                const float* __restrict__ w5, uint32_t* __restrict__ dst)
{
    int idx = blockIdx.x * blockDim.x + threadIdx.x;
    if (idx >= APACK_TOTAL) return;
    if      (idx < APACK_OFF2) pack_one(w1, dst + APACK_OFF1, idx - APACK_OFF1, 181, 128);
    else if (idx < APACK_OFF3) pack_one(w2, dst + APACK_OFF2, idx - APACK_OFF2, 309, 128);
    else if (idx < APACK_OFF4) pack_one(w3, dst + APACK_OFF3, idx - APACK_OFF3, 437, 96);
    else if (idx < APACK_OFF5) pack_one(w4, dst + APACK_OFF4, idx - APACK_OFF4, 533, 64);
    else                       pack_one(w5, dst + APACK_OFF5, idx - APACK_OFF5, 597, 32);
}

// ---------------------------------------------------------------------------
// Merged ConvTranspose2d(k=4, s=2, p=1), Cout = 2; dual-writes fp32 + packed
// ---------------------------------------------------------------------------
__global__ void upconv_both_kernel(const float* __restrict__ inF, const float* __restrict__ wF,
                                   const float* __restrict__ bF,
                                   const float* __restrict__ inU, const float* __restrict__ wU,
                                   const float* __restrict__ bU,
                                   float* __restrict__ feat)
{
    int gid = blockIdx.x * blockDim.x + threadIdx.x;
    if (gid >= Bn * HW) return;
    const int which = blockIdx.y;
    const float* in  = which ? inU : inF;
    const float* w   = which ? wU  : wF;
    const float* bias= which ? bU  : bF;
    const int Cin    = which ? PREVC : 2;
    const int choff  = which ? OFF_UPF : OFF_FLOW;

    int b = gid / HW;
    int pix = gid - b * HW;
    int y = pix / W, x = pix - (pix / W) * W;

    int iy0 = y >> 1,                        ky0 = 1 + (y & 1);
    int iy1 = (y >> 1) + ((y & 1) ? 1 : -1), ky1 = (y & 1) ? 0 : 3;
    int ix0 = x >> 1,                        kx0 = 1 + (x & 1);
    int ix1 = (x >> 1) + ((x & 1) ? 1 : -1), kx1 = (x & 1) ? 0 : 3;
    bool vy1 = (unsigned)iy1 < HIN;
    bool vx1 = (unsigned)ix1 < WIN;

    float a0 = bias[0], a1 = bias[1];
    const float* pin = in + (size_t)b * Cin * HWIN;
    int w00i = ky0 * 4 + kx0, w01i = ky0 * 4 + kx1;
    int w10i = ky1 * 4 + kx0, w11i = ky1 * 4 + kx1;
    int p00 = iy0 * WIN + ix0, p01 = iy0 * WIN + ix1;
    int p10 = iy1 * WIN + ix0, p11 = iy1 * WIN + ix1;

    for (int ci = 0; ci < Cin; ci++) {
        const float* p = pin + (size_t)ci * HWIN;
        const float* wc = w + (size_t)ci * 32;
        float v = p[p00];
        a0 += v * wc[w00i];       a1 += v * wc[16 + w00i];
        if (vx1)        { float u = p[p01]; a0 += u * wc[w01i]; a1 += u * wc[16 + w01i]; }
        if (vy1)        { float u = p[p10]; a0 += u * wc[w10i]; a1 += u * wc[16 + w10i]; }
        if (vy1 && vx1) { float u = p[p11]; a0 += u * wc[w11i]; a1 += u * wc[16 + w11i]; }
    }
    size_t o = (size_t)b * FEAT_STRIDE + (size_t)choff * HW + pix;
    feat[o]      = a0;
    feat[o + HW] = a1;
    g_half[o]      = packhl(a0);
    g_half[o + HW] = packhl(a1);
}

__global__ void copy_t1_kernel(const float* __restrict__ t1, float* __restrict__ feat)
{
    size_t i = (size_t)blockIdx.x * blockDim.x + threadIdx.x;
    const size_t n4 = (size_t)Bn * C1CH * HW / 4;
    if (i >= n4) return;
    const size_t per = (size_t)C1CH * HW / 4;
    size_t b = i / per, r = i - b * per;
    float4 v = ((const float4*)t1)[i];
    size_t o = b * (size_t)FEAT_STRIDE + (size_t)OFF_T1 * HW;
    ((float4*)(feat + o))[r] = v;
    ((uint4*)(g_half + o))[r] = make_uint4(packhl(v.x), packhl(v.y), packhl(v.z), packhl(v.w));
}

__global__ void warp_kernel(const float* __restrict__ tenTwo, const float* __restrict__ feat)
{
    int gid = blockIdx.x * blockDim.x + threadIdx.x;
    if (gid >= Bn * HW) return;
    int b = gid / HW;
    int pix = gid - b * HW;
    int y = pix / W, x = pix - (pix / W) * W;

    const float* fl = feat + (size_t)b * FEAT_STRIDE + (size_t)OFF_FLOW * HW + pix;
    float px = (float)x + fl[0]  * 1.25f;
    float py = (float)y + fl[HW] * 1.25f;
    float fx = floorf(px), fy = floorf(py);
    float wx = px - fx, wy = py - fy;
    int ix0 = (int)fx, iy0 = (int)fy;
    int ix1 = ix0 + 1, iy1 = iy0 + 1;
    bool vx0 = (unsigned)ix0 < W, vx1 = (unsigned)ix1 < W;
    bool vy0 = (unsigned)iy0 < H, vy1 = (unsigned)iy1 < H;
    float w00 = (1.f - wy) * (1.f - wx), w01 = (1.f - wy) * wx;
    float w10 = wy * (1.f - wx),         w11 = wy * wx;
    int o00 = iy0 * W + ix0, o01 = iy0 * W + ix1;
    int o10 = iy1 * W + ix0, o11 = iy1 * W + ix1;

    const float* t = tenTwo + (size_t)b * C1CH * HW;
    float* o = g_warped + (size_t)b * C1CH * HW + pix;
    for (int c = 0; c < C1CH; c++) {
        const float* tc = t + (size_t)c * HW;
        float v = 0.f;
        if (vy0 && vx0) v += tc[o00] * w00;
        if (vy0 && vx1) v += tc[o01] * w01;
        if (vy1 && vx0) v += tc[o10] * w10;
        if (vy1 && vx1) v += tc[o11] * w11;
        o[(size_t)c * HW] = v;
    }
}

__global__ __launch_bounds__(128) void corr_kernel(const float* __restrict__ tenOne,
                                                   float* __restrict__ feat)
{
    __shared__ float s_f1[4][32];
    __shared__ float s_w2[12][40];
    int tid = threadIdx.x;
    int tx = tid & 31, ty = tid >> 5;
    int x0 = blockIdx.x * 32, y0 = blockIdx.y * 4, b = blockIdx.z;

    float acc[81];
#pragma unroll
    for (int d = 0; d < 81; d++) acc[d] = 0.f;

    const float* f1 = tenOne + (size_t)b * C1CH * HW;
    const float* f2 = g_warped + (size_t)b * C1CH * HW;

    for (int c = 0; c < C1CH; c++) {
        const float* f1c = f1 + (size_t)c * HW;
        const float* f2c = f2 + (size_t)c * HW;
        __syncthreads();
        s_f1[ty][tx] = f1c[(y0 + ty) * W + x0 + tx];
#pragma unroll
        for (int i = 0; i < 4; i++) {
            int idx = tid + i * 128;
            if (idx < 480) {
                int r = idx / 40, cc = idx - (idx / 40) * 40;
                int gy = y0 - 4 + r, gx = x0 - 4 + cc;
                float v = 0.f;
                if ((unsigned)gy < H && (unsigned)gx < W) v = f2c[gy * W + gx];
                s_w2[r][cc] = v;
            }
        }
        __syncthreads();
        float a = s_f1[ty][tx];
#pragma unroll
        for (int dy = 0; dy < 9; dy++)
#pragma unroll
            for (int dx = 0; dx < 9; dx++)
                acc[dy * 9 + dx] += a * s_w2[ty + dy][tx + dx];
    }

    size_t obase = (size_t)b * FEAT_STRIDE + (size_t)OFF_VOL * HW + (y0 + ty) * W + x0 + tx;
    const float inv = 1.f / 96.f;
#pragma unroll
    for (int d = 0; d < 81; d++) {
        float v = acc[d] * inv;
        v = (v >= 0.f) ? v : 0.1f * v;
        feat[obase + (size_t)d * HW] = v;
        g_half[obase + (size_t)d * HW] = packhl(v);
    }
}

// ---------------------------------------------------------------------------
// FFMA direct 3x3 conv (conv6, Cout=2)
// ---------------------------------------------------------------------------
template <int COUT_BLK>
__global__ __launch_bounds__(256) void conv3x3_kernel(
    const float* __restrict__ in, const float* __restrict__ w,
    const float* __restrict__ bias, float* __restrict__ out,
    int Cin, int inStride, int outStride)
{
    __shared__ float s_in[18][66];
    __shared__ float s_w[COUT_BLK * 9];
    const int tid = threadIdx.x;
    const int tx = tid & 15, ty = tid >> 4;
    const int g = blockIdx.x;
    const int tileX = blockIdx.y & 1, tileY = blockIdx.y >> 1;
    const int b = blockIdx.z;
    const int x0 = tileX * 64, y0 = tileY * 16;

    const float* inB = in + (size_t)b * inStride;
    float acc[COUT_BLK][4];
#pragma unroll
    for (int c = 0; c < COUT_BLK; c++)
#pragma unroll
        for (int p = 0; p < 4; p++) acc[c][p] = 0.f;

    for (int ci = 0; ci < Cin; ci++) {
        const float* ch = inB + (size_t)ci * HW;
#pragma unroll
        for (int i = 0; i < 5; i++) {
            int idx = tid + i * 256;
            if (idx < 18 * 66) {
                int r = idx / 66, c = idx - (idx / 66) * 66;
                int gy = y0 - 1 + r, gx = x0 - 1 + c;
                float v = 0.f;
                if ((unsigned)gy < H && (unsigned)gx < W) v = ch[gy * W + gx];
                s_in[r][c] = v;
            }
        }
        if (tid < COUT_BLK * 9)
            s_w[tid] = w[((size_t)(g * COUT_BLK + tid / 9) * Cin + ci) * 9 + tid % 9];
        __syncthreads();

        float r0[6], r1[6], r2[6];
#pragma unroll
        for (int k = 0; k < 6; k++) {
            r0[k] = s_in[ty][tx * 4 + k];
            r1[k] = s_in[ty + 1][tx * 4 + k];
            r2[k] = s_in[ty + 2][tx * 4 + k];
        }
#pragma unroll
        for (int co = 0; co < COUT_BLK; co++) {
            float w0 = s_w[co * 9 + 0], w1v = s_w[co * 9 + 1], w2v = s_w[co * 9 + 2];
            float w3v = s_w[co * 9 + 3], w4v = s_w[co * 9 + 4], w5v = s_w[co * 9 + 5];
            float w6v = s_w[co * 9 + 6], w7v = s_w[co * 9 + 7], w8v = s_w[co * 9 + 8];
#pragma unroll
            for (int p = 0; p < 4; p++) {
                float s = acc[co][p];
                s += w0  * r0[p]; s += w1v * r0[p + 1]; s += w2v * r0[p + 2];
                s += w3v * r1[p]; s += w4v * r1[p + 1]; s += w5v * r1[p + 2];
                s += w6v * r2[p]; s += w7v * r2[p + 1]; s += w8v * r2[p + 2];
                acc[co][p] = s;
            }
        }
        __syncthreads();
    }

#pragma unroll
    for (int co = 0; co < COUT_BLK; co++) {
        float bi = bias[g * COUT_BLK + co];
        float* o = out + (size_t)b * outStride + (size_t)(g * COUT_BLK + co) * HW
                 + (y0 + ty) * W + x0 + tx * 4;
#pragma unroll
        for (int p = 0; p < 4; p++) {
            float v = acc[co][p] + bi;
            o[p] = (v >= 0.f) ? v : 0.1f * v;
        }
    }
}

// ---------------------------------------------------------------------------
// conv_mma4: half-row tiles (N = 64 pixels), NW = 1, warp tile 32x64.
// MW = Cout/32 warps. 1024 CTAs -> fine-grained wave balance. Static smem.
// Same 2-term fp16 split, same Apack layout, same staging scheme (SROW = 72).
// ---------------------------------------------------------------------------
template <int Cin, int Cout, int THREADS, int MINB>
__global__ __launch_bounds__(THREADS, MINB) void conv_mma4_kernel(
    const uint32_t* __restrict__ inBase,
    const uint4* __restrict__ Apack,
    const float* __restrict__ bias,
    float* __restrict__ outBase,
    uint32_t* __restrict__ outHalfBase)
{
    constexpr int nC  = (Cin + 15) / 16;
    constexpr int MFT = Cout / 16;
    constexpr int SR  = 72;               // u32 per staged row (== 8 mod 32)
    constexpr int BUF = 16 * 3 * SR;      // 3456 u32 per buffer

    __shared__ uint32_t raw[2 * BUF];
    const int tid = threadIdx.x, lane = tid & 31, wrp = tid >> 5;
    const int wm0 = wrp * 32;
    const int y  = blockIdx.x >> 1;
    const int x0 = (blockIdx.x & 1) << 6;
    const int b  = blockIdx.y;
    const uint32_t* inB = inBase + (size_t)b * FEAT_STRIDE;
    const uint32_t rawAddr = smem_u32(raw);
    const uint4* apw = Apack + (size_t)(wrp * 2) * 32 + lane;

    float acc[2][8][4];
#pragma unroll
    for (int mi = 0; mi < 2; mi++)
#pragma unroll
        for (int nf = 0; nf < 8; nf++)
#pragma unroll
            for (int p = 0; p < 4; p++) acc[mi][nf][p] = 0.f;

    auto stage = [&](int kt, int bufsel) {
        // interior: 16 ch x 3 rows x 16 float4 (64 pixels)
        for (int i = tid; i < 768; i += THREADS) {
            int c = i / 48;
            int rem = i - c * 48;
            int r = rem >> 4, v = rem & 15;
            int ci = kt * 16 + c;
            int yr = y + r - 1;
            uint32_t foff = (uint32_t)(bufsel * BUF + (c * 3 + r) * SR + 4 + v * 4);
            if (ci < Cin && (unsigned)yr < (unsigned)H)
                cp_async16(rawAddr + foff * 4, inB + (size_t)ci * HW + yr * W + x0 + v * 4);
            else
                *(uint4*)(raw + foff) = make_uint4(0u, 0u, 0u, 0u);
        }
        // edges: 16 ch x 3 rows x 2 (x0-1 at [3], x0+64 at [68])
        for (int i = tid; i < 96; i += THREADS) {
            int c = i / 6;
            int rem = i - c * 6;
            int r = rem >> 1, s = rem & 1;
            int ci = kt * 16 + c;
            int yr = y + r - 1;
            int x = s ? (x0 + 64) : (x0 - 1);
            uint32_t foff = (uint32_t)(bufsel * BUF + (c * 3 + r) * SR + (s ? 68 : 3));
            if (ci < Cin && (unsigned)yr < (unsigned)H && (unsigned)x < (unsigned)W)
                cp_async4(rawAddr + foff * 4, inB + (size_t)ci * HW + yr * W + x);
            else
                raw[foff] = 0u;
        }
    };

    stage(0, 0);
    CP_COMMIT();

    const int t = lane & 3;
    const int nbase = (lane >> 2) + 3;

    uint4 ah0, ah1;
    { const uint4* p = apw; ah0 = p[0]; ah1 = p[32]; }

    for (int kt = 0; kt < nC; kt++) {
        const int buf = kt & 1;
        if (kt + 1 < nC) {
            stage(kt + 1, buf ^ 1);
            CP_COMMIT();
            CP_WAIT1();
        } else {
            CP_WAIT0();
        }
        __syncthreads();

        const uint32_t* rb = raw + buf * BUF;

#pragma unroll
        for (int ks = 0; ks < 9; ks++) {
            uint4 nh0, nh1;
            {
                int nkt = kt, nks = ks + 1;
                if (nks == 9) { nkt = kt + 1; nks = 0; }
                if (nkt < nC) {
                    const uint4* p = apw + (size_t)((nkt * 9 + nks) * MFT) * 32;
                    nh0 = p[0]; nh1 = p[32];
                } else {
                    nh0 = nh1 = make_uint4(0u, 0u, 0u, 0u);
                }
            }

            int j0 = ks * 16 + 2 * t, j1 = j0 + 8;
            const uint32_t* q0;
            const uint32_t* q1;
            const uint32_t* q2;
            const uint32_t* q3;
            {
                int c = j0 / 9, tp = j0 - c * 9;
                q0 = rb + (c * 3 + tp / 3) * SR + (tp % 3) + nbase;
            }
            {
                int jj = j0 + 1;
                int c = jj / 9, tp = jj - c * 9;
                q1 = rb + (c * 3 + tp / 3) * SR + (tp % 3) + nbase;
            }
            {
                int c = j1 / 9, tp = j1 - c * 9;
                q2 = rb + (c * 3 + tp / 3) * SR + (tp % 3) + nbase;
            }
            {
                int jj = j1 + 1;
                int c = jj / 9, tp = jj - c * 9;
                q3 = rb + (c * 3 + tp / 3) * SR + (tp % 3) + nbase;
            }

#pragma unroll
            for (int nf = 0; nf < 8; nf += 2) {
                uint32_t a00 = q0[nf * 8],     a01 = q1[nf * 8];
                uint32_t a10 = q2[nf * 8],     a11 = q3[nf * 8];
                uint32_t c00 = q0[nf * 8 + 8], c01 = q1[nf * 8 + 8];
                uint32_t c10 = q2[nf * 8 + 8], c11 = q3[nf * 8 + 8];
                uint32_t bhA0 = __byte_perm(a00, a01, 0x5410);
                uint32_t blA0 = __byte_perm(a00, a01, 0x7632);
                uint32_t bhA1 = __byte_perm(a10, a11, 0x5410);
                uint32_t blA1 = __byte_perm(a10, a11, 0x7632);
                uint32_t bhB0 = __byte_perm(c00, c01, 0x5410);
                uint32_t blB0 = __byte_perm(c00, c01, 0x7632);
                uint32_t bhB1 = __byte_perm(c10, c11, 0x5410);
                uint32_t blB1 = __byte_perm(c10, c11, 0x7632);
                // hi phase (acc reuse distance 4), then lo phase
                MMA_F16(acc[0][nf],     ah0.x, ah0.y, ah0.z, ah0.w, bhA0, bhA1);
                MMA_F16(acc[1][nf],     ah1.x, ah1.y, ah1.z, ah1.w, bhA0, bhA1);
                MMA_F16(acc[0][nf + 1], ah0.x, ah0.y, ah0.z, ah0.w, bhB0, bhB1);
                MMA_F16(acc[1][nf + 1], ah1.x, ah1.y, ah1.z, ah1.w, bhB0, bhB1);
                MMA_F16(acc[0][nf],     ah0.x, ah0.y, ah0.z, ah0.w, blA0, blA1);
                MMA_F16(acc[1][nf],     ah1.x, ah1.y, ah1.z, ah1.w, blA0, blA1);
                MMA_F16(acc[0][nf + 1], ah0.x, ah0.y, ah0.z, ah0.w, blB0, blB1);
                MMA_F16(acc[1][nf + 1], ah1.x, ah1.y, ah1.z, ah1.w, blB0, blB1);
            }
            ah0 = nh0; ah1 = nh1;
        }
        __syncthreads();
    }

    // ---- epilogue: bias + leaky; dual-write fp32 feat + packed g_half ----
    const int q = lane & 3, g2 = lane >> 2;
    float* outB = outBase + (size_t)b * FEAT_STRIDE;
    uint32_t* outH = outHalfBase + (size_t)b * FEAT_STRIDE;
#pragma unroll
    for (int mi = 0; mi < 2; mi++) {
        int m0 = wm0 + mi * 16 + g2;
        float bLo = __ldg(bias + m0), bHi = __ldg(bias + m0 + 8);
        float* o0 = outB + (size_t)m0 * HW;
        float* o1 = o0 + 8 * HW;
        uint32_t* h0 = outH + (size_t)m0 * HW;
        uint32_t* h1 = h0 + 8 * HW;
#pragma unroll
        for (int nf = 0; nf < 8; nf++) {
            int off = y * W + x0 + nf * 8 + 2 * q;
            float v0 = acc[mi][nf][0] + bLo, v1 = acc[mi][nf][1] + bLo;
            float v2 = acc[mi][nf][2] + bHi, v3 = acc[mi][nf][3] + bHi;
            v0 = (v0 >= 0.f) ? v0 : 0.1f * v0;
            v1 = (v1 >= 0.f) ? v1 : 0.1f * v1;
            v2 = (v2 >= 0.f) ? v2 : 0.1f * v2;
            v3 = (v3 >= 0.f) ? v3 : 0.1f * v3;
            *(float2*)(o0 + off) = make_float2(v0, v1);
            *(float2*)(o1 + off) = make_float2(v2, v3);
            *(uint2*)(h0 + off) = make_uint2(packhl(v0), packhl(v1));
            *(uint2*)(h1 + off) = make_uint2(packhl(v2), packhl(v3));
        }
    }
}

// ---------------------------------------------------------------------------
// conv_mma3: full-row kernel (kept for s4/s5)
// ---------------------------------------------------------------------------
template <int Cin, int Cout, int NW, int NROWS, int THREADS, int MINB>
__global__ __launch_bounds__(THREADS, MINB) void conv_mma3_kernel(
    const uint32_t* __restrict__ inBase,
    const uint4* __restrict__ Apack,
    const float* __restrict__ bias,
    float* __restrict__ outBase,
    uint32_t* __restrict__ outHalfBase)
{
    constexpr int nC    = (Cin + 15) / 16;
    constexpr int R     = NROWS + 2;
    constexpr int SROW  = 136;
    constexpr int BUFSZ = 16 * R * SROW;
    constexpr int MFT   = Cout / 16;

    extern __shared__ uint32_t raw[];
    const int tid = threadIdx.x, lane = tid & 31, wrp = tid >> 5;
    const int wm = wrp / NW, wn = wrp % NW;
    const int wm0 = wm * 32, wn0 = wn * 64;
    const int wrow = wn0 >> 7, wcol = wn0 & 127;
    const int yBase = blockIdx.x * NROWS, b = blockIdx.y;
    const uint32_t* inB = inBase + (size_t)b * FEAT_STRIDE;
    const uint32_t rawAddr = smem_u32(raw);

    const uint4* apw = Apack + (size_t)(wm * 2) * 32 + lane;

    for (int i = tid; i < 2 * 16 * R; i += THREADS) {
        raw[i * SROW + 3]   = 0u;
        raw[i * SROW + 132] = 0u;
    }

    float acc[2][8][4];
#pragma unroll
    for (int mi = 0; mi < 2; mi++)
#pragma unroll
        for (int ni = 0; ni < 8; ni++)
#pragma unroll
            for (int p = 0; p < 4; p++) acc[mi][ni][p] = 0.f;

    auto stage = [&](int kt, int bufsel) {
        const int total = 16 * R * 32;
        for (int i = tid; i < total; i += THREADS) {
            int c   = i / (R * 32);
            int rem = i - c * (R * 32);
            int rr  = rem >> 5, v = rem & 31;
            int ci  = kt * 16 + c;
            int gy  = yBase + rr - 1;
            int foff = bufsel * BUFSZ + (c * R + rr) * SROW + 4 + v * 4;
            if (ci < Cin && (unsigned)gy < (unsigned)H) {
                cp_async16(rawAddr + (uint32_t)(foff * 4),
                           inB + (size_t)ci * HW + gy * W + v * 4);
            } else {
                *(uint4*)(raw + foff) = make_uint4(0u, 0u, 0u, 0u);
            }
        }
    };

    stage(0, 0);
    CP_COMMIT();

    const int t = lane & 3;
    const int nbase = wcol + (lane >> 2);

    uint4 ah0, ah1;
    {
        const uint4* p = apw;
        ah0 = p[0]; ah1 = p[32];
    }

    for (int kt = 0; kt < nC; kt++) {
        const int buf = kt & 1;
        if (kt + 1 < nC) {
            stage(kt + 1, buf ^ 1);
            CP_COMMIT();
            CP_WAIT1();
        } else {
            CP_WAIT0();
        }
        __syncthreads();

        const uint32_t* rb = raw + buf * BUFSZ;

#pragma unroll
        for (int ks = 0; ks < 9; ks++) {
            uint4 nh0, nh1;
            {
                int nkt = kt, nks = ks + 1;
                if (nks == 9) { nkt = kt + 1; nks = 0; }
                if (nkt < nC) {
                    const uint4* p = apw + (size_t)((nkt * 9 + nks) * MFT) * 32;
                    nh0 = p[0]; nh1 = p[32];
                } else {
                    nh0 = nh1 = make_uint4(0u, 0u, 0u, 0u);
                }
            }

            int j0 = ks * 16 + 2 * t, j1 = j0 + 8;
            const uint32_t* q0;
            const uint32_t* q1;
            const uint32_t* q2;
            const uint32_t* q3;
            {
                int c = j0 / 9, tp = j0 - c * 9;
                q0 = rb + (c * R + wrow + tp / 3) * SROW + (tp % 3) + 3 + nbase;
            }
            {
                int jj = j0 + 1;
                int c = jj / 9, tp = jj - c * 9;
                q1 = rb + (c * R + wrow + tp / 3) * SROW + (tp % 3) + 3 + nbase;
            }
            {
                int c = j1 / 9, tp = j1 - c * 9;
                q2 = rb + (c * R + wrow + tp / 3) * SROW + (tp % 3) + 3 + nbase;
            }
            {
                int jj = j1 + 1;
                int c = jj / 9, tp = jj - c * 9;
                q3 = rb + (c * R + wrow + tp / 3) * SROW + (tp % 3) + 3 + nbase;
            }

#pragma unroll
            for (int nf = 0; nf < 8; nf++) {
                uint32_t w00 = q0[nf * 8], w01 = q1[nf * 8];
                uint32_t w10 = q2[nf * 8], w11 = q3[nf * 8];
                uint32_t bh0 = __byte_perm(w00, w01, 0x5410);
                uint32_t bl0 = __byte_perm(w00, w01, 0x7632);
                uint32_t bh1 = __byte_perm(w10, w11, 0x5410);
                uint32_t bl1 = __byte_perm(w10, w11, 0x7632);
                MMA_F16(acc[0][nf], ah0.x, ah0.y, ah0.z, ah0.w, bh0, bh1);
                MMA_F16(acc[1][nf], ah1.x, ah1.y, ah1.z, ah1.w, bh0, bh1);
                MMA_F16(acc[0][nf], ah0.x, ah0.y, ah0.z, ah0.w, bl0, bl1);
                MMA_F16(acc[1][nf], ah1.x, ah1.y, ah1.z, ah1.w, bl0, bl1);
            }
            ah0 = nh0; ah1 = nh1;
        }
        __syncthreads();
    }

    const int q = lane & 3, g2 = lane >> 2;
    float* outB = outBase + (size_t)b * FEAT_STRIDE;
    uint32_t* outH = outHalfBase + (size_t)b * FEAT_STRIDE;
#pragma unroll
    for (int mi = 0; mi < 2; mi++) {
        int m0 = wm0 + mi * 16 + g2;
        float bLo = __ldg(bias + m0), bHi = __ldg(bias + m0 + 8);
        float* o0 = outB + (size_t)m0 * HW;
        float* o1 = o0 + 8 * HW;
        uint32_t* h0 = outH + (size_t)m0 * HW;
        uint32_t* h1 = h0 + 8 * HW;
#pragma unroll
        for (int ni = 0; ni < 8; ni++) {
            int n = wn0 + ni * 8 + 2 * q;
            int off = (yBase + (n >> 7)) * W + (n & 127);
            float v0 = acc[mi][ni][0] + bLo, v1 = acc[mi][ni][1] + bLo;
            float v2 = acc[mi][ni][2] + bHi, v3 = acc[mi][ni][3] + bHi;
            v0 = (v0 >= 0.f) ? v0 : 0.1f * v0;
            v1 = (v1 >= 0.f) ? v1 : 0.1f * v1;
            v2 = (v2 >= 0.f) ? v2 : 0.1f * v2;
            v3 = (v3 >= 0.f) ? v3 : 0.1f * v3;
            *(float2*)(o0 + off) = make_float2(v0, v1);
            *(float2*)(o1 + off) = make_float2(v2, v3);
            *(uint2*)(h0 + off) = make_uint2(packhl(v0), packhl(v1));
            *(uint2*)(h1 + off) = make_uint2(packhl(v2), packhl(v3));
        }
    }
}

// ---------------------------------------------------------------------------
// Launch
// ---------------------------------------------------------------------------
extern "C" void kernel_launch(void* const* d_in, const int* in_sizes, int n_in,
                              void* d_out, int out_size)
{
    (void)in_sizes; (void)n_in; (void)out_size;
    const float* tenOne    = (const float*)d_in[0];
    const float* tenTwo    = (const float*)d_in[1];
    const float* prev_flow = (const float*)d_in[2];
    const float* prev_feat = (const float*)d_in[3];
    const float* w_upflow  = (const float*)d_in[4];
    const float* b_upflow  = (const float*)d_in[5];
    const float* w_upfeat  = (const float*)d_in[6];
    const float* b_upfeat  = (const float*)d_in[7];
    const float* w1 = (const float*)d_in[8];   const float* b1 = (const float*)d_in[9];
    const float* w2 = (const float*)d_in[10];  const float* b2 = (const float*)d_in[11];
    const float* w3 = (const float*)d_in[12];  const float* b3 = (const float*)d_in[13];
    const float* w4 = (const float*)d_in[14];  const float* b4 = (const float*)d_in[15];
    const float* w5 = (const float*)d_in[16];  const float* b5 = (const float*)d_in[17];
    const float* w6 = (const float*)d_in[18];  const float* b6 = (const float*)d_in[19];

    float* flow = (float*)d_out;
    float* feat = flow + (size_t)Bn * 2 * HW;

    uint32_t* apack;
    cudaGetSymbolAddress((void**)&apack, g_Apack);
    uint32_t* half;
    cudaGetSymbolAddress((void**)&half, g_half);

    const int SMA = 52224, SMB = 69632;
    cudaFuncSetAttribute(conv_mma3_kernel<533, 64, 2, 1, 128, 3>, cudaFuncAttributeMaxDynamicSharedMemorySize, SMA);
    cudaFuncSetAttribute(conv_mma3_kernel<597, 32, 4, 2, 128, 3>, cudaFuncAttributeMaxDynamicSharedMemorySize, SMB);

    const int NPIX = Bn * HW;

    // 0. merged weight pre-pack
    pack_all_kernel<<<(APACK_TOTAL + 255) / 256, 256>>>(w1, w2, w3, w4, w5, apack);
    // 1. both upconvs (dual-write)
    upconv_both_kernel<<<dim3((NPIX + 255) / 256, 2), 256>>>(
        prev_flow, w_upflow, b_upflow, prev_feat, w_upfeat, b_upfeat, feat);
    // 2. tenOne (dual-write)
    {
        size_t n4 = (size_t)Bn * C1CH * HW / 4;
        copy_t1_kernel<<<(unsigned)((n4 + 255) / 256), 256>>>(tenOne, feat);
    }
    // 3. warp tenTwo
    warp_kernel<<<(NPIX + 255) / 256, 256>>>(tenTwo, feat);
    // 4. correlation (dual-write)
    corr_kernel<<<dim3(W / 32, H / 4, Bn), 128>>>(tenOne, feat);

    // 5-9. fp16 2-term mma conv tower
    conv_mma4_kernel<181, 128, 128, 4><<<dim3(128, Bn), 128>>>(
        half + (size_t)OFF_VOL * HW, (const uint4*)(apack + APACK_OFF1), b1,
        feat + (size_t)OFF_C1 * HW, half + (size_t)OFF_C1 * HW);
    conv_mma4_kernel<309, 128, 128, 4><<<dim3(128, Bn), 128>>>(
        half + (size_t)OFF_C1 * HW, (const uint4*)(apack + APACK_OFF2), b2,
        feat + (size_t)OFF_C2 * HW, half + (size_t)OFF_C2 * HW);
    conv_mma4_kernel<437, 96, 96, 5><<<dim3(128, Bn), 96>>>(
        half + (size_t)OFF_C2 * HW, (const uint4*)(apack + APACK_OFF3), b3,
        feat + (size_t)OFF_C3 * HW, half + (size_t)OFF_C3 * HW);
    conv_mma3_kernel<533, 64, 2, 1, 128, 3><<<dim3(64, Bn), 128, SMA>>>(
        half + (size_t)OFF_C3 * HW, (const uint4*)(apack + APACK_OFF4), b4,
        feat + (size_t)OFF_C4 * HW, half + (size_t)OFF_C4 * HW);
    conv_mma3_kernel<597, 32, 4, 2, 128, 3><<<dim3(32, Bn), 128, SMB>>>(
        half + (size_t)OFF_C4 * HW, (const uint4*)(apack + APACK_OFF5), b5,
        feat + (size_t)OFF_C5 * HW, half + (size_t)OFF_C5 * HW);

    // 10. conv6 (Cout=2) -> flow, FFMA path
    conv3x3_kernel<2><<<dim3(1, 8, Bn), 256>>>(
        feat + (size_t)OFF_C5 * HW, w6, b6, flow,
        629, FEAT_STRIDE, 2 * HW);
}

// round 13
// speedup vs baseline: 1.4330x; 1.0100x over previous
#include <cuda_runtime.h>
#include <cuda_fp16.h>
#include <math.h>
#include <stdint.h>

// ---------------------------------------------------------------------------
// Problem dims (fixed by the dataset)
// ---------------------------------------------------------------------------
#define Bn 8
#define H 64
#define W 128
#define HW (H * W)            // 8192
#define C1CH 96
#define HIN 32
#define WIN 64
#define HWIN (HIN * WIN)
#define PREVC 661

#define FEAT_C 629
#define FEAT_STRIDE (FEAT_C * HW)

// [c5(32) | c4(64) | c3(96) | c2(128) | c1(128) | vol(81) | tenOne(96) | flow(2) | upfeat(2)]
#define OFF_C5   0
#define OFF_C4   32
#define OFF_C3   96
#define OFF_C2   192
#define OFF_C1   320
#define OFF_VOL  448
#define OFF_T1   529
#define OFF_FLOW 625
#define OFF_UPF  627

__device__ float g_warped[(size_t)Bn * C1CH * HW];

// packed (h,l) fp16 shadow of feat (u32 per pixel; hot path uses h only)
__device__ uint32_t g_half[(size_t)Bn * FEAT_C * HW];

// pre-packed fp16 (hi only) A-fragments, chunk = 144 k (16 channels x 9 taps)
#define APACK_OFF1 0
#define APACK_OFF2 110592      // + 12*9*8*128
#define APACK_OFF3 294912      // + 20*9*8*128
#define APACK_OFF4 488448      // + 28*9*6*128
#define APACK_OFF5 645120      // + 34*9*4*128
#define APACK_TOTAL 732672     // + 38*9*2*128
__device__ uint32_t g_Apack[APACK_TOTAL];

// ---------------------------------------------------------------------------
// helpers
// ---------------------------------------------------------------------------
__device__ __forceinline__ uint32_t smem_u32(const void* p) {
    uint32_t a;
    asm("{ .reg .u64 t; cvta.to.shared.u64 t, %1; cvt.u32.u64 %0, t; }" : "=r"(a) : "l"(p));
    return a;
}
__device__ __forceinline__ void cp_async16(uint32_t dst, const void* src) {
    asm volatile("cp.async.ca.shared.global [%0], [%1], 16;" :: "r"(dst), "l"(src));
}
__device__ __forceinline__ void cp_async4(uint32_t dst, const void* src) {
    asm volatile("cp.async.ca.shared.global [%0], [%1], 4;" :: "r"(dst), "l"(src));
}
#define CP_COMMIT() asm volatile("cp.async.commit_group;")
#define CP_WAIT0()  asm volatile("cp.async.wait_group 0;")
#define CP_WAIT1()  asm volatile("cp.async.wait_group 1;")

__device__ __forceinline__ uint32_t packhl(float v) {
    __half h = __float2half_rn(v);
    __half l = __float2half_rn(v - __half2float(h));
    return (uint32_t)__half_as_ushort(h) | ((uint32_t)__half_as_ushort(l) << 16);
}

#define MMA_F16(c, a0, a1, a2, a3, b0v, b1v) \
    asm volatile( \
        "mma.sync.aligned.m16n8k16.row.col.f32.f16.f16.f32 " \
        "{%0,%1,%2,%3}, {%4,%5,%6,%7}, {%8,%9}, {%0,%1,%2,%3};" \
        : "+f"((c)[0]), "+f"((c)[1]), "+f"((c)[2]), "+f"((c)[3]) \
        : "r"(a0), "r"(a1), "r"(a2), "r"(a3), \
          "r"(b0v), "r"(b1v))

// ---------------------------------------------------------------------------
// Merged weight pre-pack (all 5 stages, one launch), hi fp16 only.
// ---------------------------------------------------------------------------
__device__ __forceinline__ void pack_one(const float* w, uint32_t* dst, int idx,
                                         int Cin, int Cout)
{
    int MFT = Cout >> 4;
    int reg = idx & 3, lane = (idx >> 2) & 31;
    int u = idx >> 7;
    int mf = u % MFT;
    int v3 = u / MFT;
    int ks = v3 % 9, kt = v3 / 9;
    int m = mf * 16 + (lane >> 2) + 8 * (reg & 1);
    int k = kt * 144 + ks * 16 + (lane & 3) * 2 + 8 * (reg >> 1);
    int K = Cin * 9;
    float v0 = (k     < K) ? w[(size_t)m * K + k]     : 0.f;
    float v1 = (k + 1 < K) ? w[(size_t)m * K + k + 1] : 0.f;
    __half h0 = __float2half_rn(v0), h1 = __float2half_rn(v1);
    dst[idx] = (uint32_t)__half_as_ushort(h0) | ((uint32_t)__half_as_ushort(h1) << 16);
}

__global__ void pack_all_kernel(const float* __restrict__ w1, const float* __restrict__ w2,
                                const float* __restrict__ w3, const float* __restrict__ w4,
                                const float* __restrict__ w5, uint32_t* __restrict__ dst)
{
    int idx = blockIdx.x * blockDim.x + threadIdx.x;
    if (idx >= APACK_TOTAL) return;
    if      (idx < APACK_OFF2) pack_one(w1, dst + APACK_OFF1, idx - APACK_OFF1, 181, 128);
    else if (idx < APACK_OFF3) pack_one(w2, dst + APACK_OFF2, idx - APACK_OFF2, 309, 128);
    else if (idx < APACK_OFF4) pack_one(w3, dst + APACK_OFF3, idx - APACK_OFF3, 437, 96);
    else if (idx < APACK_OFF5) pack_one(w4, dst + APACK_OFF4, idx - APACK_OFF4, 533, 64);
    else                       pack_one(w5, dst + APACK_OFF5, idx - APACK_OFF5, 597, 32);
}

// ---------------------------------------------------------------------------
// Merged ConvTranspose2d(k=4, s=2, p=1), Cout = 2; dual-writes fp32 + packed
// ---------------------------------------------------------------------------
__global__ void upconv_both_kernel(const float* __restrict__ inF, const float* __restrict__ wF,
                                   const float* __restrict__ bF,
                                   const float* __restrict__ inU, const float* __restrict__ wU,
                                   const float* __restrict__ bU,
                                   float* __restrict__ feat)
{
    int gid = blockIdx.x * blockDim.x + threadIdx.x;
    if (gid >= Bn * HW) return;
    const int which = blockIdx.y;
    const float* in  = which ? inU : inF;
    const float* w   = which ? wU  : wF;
    const float* bias= which ? bU  : bF;
    const int Cin    = which ? PREVC : 2;
    const int choff  = which ? OFF_UPF : OFF_FLOW;

    int b = gid / HW;
    int pix = gid - b * HW;
    int y = pix / W, x = pix - (pix / W) * W;

    int iy0 = y >> 1,                        ky0 = 1 + (y & 1);
    int iy1 = (y >> 1) + ((y & 1) ? 1 : -1), ky1 = (y & 1) ? 0 : 3;
    int ix0 = x >> 1,                        kx0 = 1 + (x & 1);
    int ix1 = (x >> 1) + ((x & 1) ? 1 : -1), kx1 = (x & 1) ? 0 : 3;
    bool vy1 = (unsigned)iy1 < HIN;
    bool vx1 = (unsigned)ix1 < WIN;

    float a0 = bias[0], a1 = bias[1];
    const float* pin = in + (size_t)b * Cin * HWIN;
    int w00i = ky0 * 4 + kx0, w01i = ky0 * 4 + kx1;
    int w10i = ky1 * 4 + kx0, w11i = ky1 * 4 + kx1;
    int p00 = iy0 * WIN + ix0, p01 = iy0 * WIN + ix1;
    int p10 = iy1 * WIN + ix0, p11 = iy1 * WIN + ix1;

    for (int ci = 0; ci < Cin; ci++) {
        const float* p = pin + (size_t)ci * HWIN;
        const float* wc = w + (size_t)ci * 32;
        float v = p[p00];
        a0 += v * wc[w00i];       a1 += v * wc[16 + w00i];
        if (vx1)        { float u = p[p01]; a0 += u * wc[w01i]; a1 += u * wc[16 + w01i]; }
        if (vy1)        { float u = p[p10]; a0 += u * wc[w10i]; a1 += u * wc[16 + w10i]; }
        if (vy1 && vx1) { float u = p[p11]; a0 += u * wc[w11i]; a1 += u * wc[16 + w11i]; }
    }
    size_t o = (size_t)b * FEAT_STRIDE + (size_t)choff * HW + pix;
    feat[o]      = a0;
    feat[o + HW] = a1;
    g_half[o]      = packhl(a0);
    g_half[o + HW] = packhl(a1);
}

__global__ void copy_t1_kernel(const float* __restrict__ t1, float* __restrict__ feat)
{
    size_t i = (size_t)blockIdx.x * blockDim.x + threadIdx.x;
    const size_t n4 = (size_t)Bn * C1CH * HW / 4;
    if (i >= n4) return;
    const size_t per = (size_t)C1CH * HW / 4;
    size_t b = i / per, r = i - b * per;
    float4 v = ((const float4*)t1)[i];
    size_t o = b * (size_t)FEAT_STRIDE + (size_t)OFF_T1 * HW;
    ((float4*)(feat + o))[r] = v;
    ((uint4*)(g_half + o))[r] = make_uint4(packhl(v.x), packhl(v.y), packhl(v.z), packhl(v.w));
}

__global__ void warp_kernel(const float* __restrict__ tenTwo, const float* __restrict__ feat)
{
    int gid = blockIdx.x * blockDim.x + threadIdx.x;
    if (gid >= Bn * HW) return;
    int b = gid / HW;
    int pix = gid - b * HW;
    int y = pix / W, x = pix - (pix / W) * W;

    const float* fl = feat + (size_t)b * FEAT_STRIDE + (size_t)OFF_FLOW * HW + pix;
    float px = (float)x + fl[0]  * 1.25f;
    float py = (float)y + fl[HW] * 1.25f;
    float fx = floorf(px), fy = floorf(py);
    float wx = px - fx, wy = py - fy;
    int ix0 = (int)fx, iy0 = (int)fy;
    int ix1 = ix0 + 1, iy1 = iy0 + 1;
    bool vx0 = (unsigned)ix0 < W, vx1 = (unsigned)ix1 < W;
    bool vy0 = (unsigned)iy0 < H, vy1 = (unsigned)iy1 < H;
    float w00 = (1.f - wy) * (1.f - wx), w01 = (1.f - wy) * wx;
    float w10 = wy * (1.f - wx),         w11 = wy * wx;
    int o00 = iy0 * W + ix0, o01 = iy0 * W + ix1;
    int o10 = iy1 * W + ix0, o11 = iy1 * W + ix1;

    const float* t = tenTwo + (size_t)b * C1CH * HW;
    float* o = g_warped + (size_t)b * C1CH * HW + pix;
    for (int c = 0; c < C1CH; c++) {
        const float* tc = t + (size_t)c * HW;
        float v = 0.f;
        if (vy0 && vx0) v += tc[o00] * w00;
        if (vy0 && vx1) v += tc[o01] * w01;
        if (vy1 && vx0) v += tc[o10] * w10;
        if (vy1 && vx1) v += tc[o11] * w11;
        o[(size_t)c * HW] = v;
    }
}

__global__ __launch_bounds__(128) void corr_kernel(const float* __restrict__ tenOne,
                                                   float* __restrict__ feat)
{
    __shared__ float s_f1[4][32];
    __shared__ float s_w2[12][40];
    int tid = threadIdx.x;
    int tx = tid & 31, ty = tid >> 5;
    int x0 = blockIdx.x * 32, y0 = blockIdx.y * 4, b = blockIdx.z;

    float acc[81];
#pragma unroll
    for (int d = 0; d < 81; d++) acc[d] = 0.f;

    const float* f1 = tenOne + (size_t)b * C1CH * HW;
    const float* f2 = g_warped + (size_t)b * C1CH * HW;

    for (int c = 0; c < C1CH; c++) {
        const float* f1c = f1 + (size_t)c * HW;
        const float* f2c = f2 + (size_t)c * HW;
        __syncthreads();
        s_f1[ty][tx] = f1c[(y0 + ty) * W + x0 + tx];
#pragma unroll
        for (int i = 0; i < 4; i++) {
            int idx = tid + i * 128;
            if (idx < 480) {
                int r = idx / 40, cc = idx - (idx / 40) * 40;
                int gy = y0 - 4 + r, gx = x0 - 4 + cc;
                float v = 0.f;
                if ((unsigned)gy < H && (unsigned)gx < W) v = f2c[gy * W + gx];
                s_w2[r][cc] = v;
            }
        }
        __syncthreads();
        float a = s_f1[ty][tx];
#pragma unroll
        for (int dy = 0; dy < 9; dy++)
#pragma unroll
            for (int dx = 0; dx < 9; dx++)
                acc[dy * 9 + dx] += a * s_w2[ty + dy][tx + dx];
    }

    size_t obase = (size_t)b * FEAT_STRIDE + (size_t)OFF_VOL * HW + (y0 + ty) * W + x0 + tx;
    const float inv = 1.f / 96.f;
#pragma unroll
    for (int d = 0; d < 81; d++) {
        float v = acc[d] * inv;
        v = (v >= 0.f) ? v : 0.1f * v;
        feat[obase + (size_t)d * HW] = v;
        g_half[obase + (size_t)d * HW] = packhl(v);
    }
}

// ---------------------------------------------------------------------------
// FFMA direct 3x3 conv (conv6, Cout=2)
// ---------------------------------------------------------------------------
template <int COUT_BLK>
__global__ __launch_bounds__(256) void conv3x3_kernel(
    const float* __restrict__ in, const float* __restrict__ w,
    const float* __restrict__ bias, float* __restrict__ out,
    int Cin, int inStride, int outStride)
{
    __shared__ float s_in[18][66];
    __shared__ float s_w[COUT_BLK * 9];
    const int tid = threadIdx.x;
    const int tx = tid & 15, ty = tid >> 4;
    const int g = blockIdx.x;
    const int tileX = blockIdx.y & 1, tileY = blockIdx.y >> 1;
    const int b = blockIdx.z;
    const int x0 = tileX * 64, y0 = tileY * 16;

    const float* inB = in + (size_t)b * inStride;
    float acc[COUT_BLK][4];
#pragma unroll
    for (int c = 0; c < COUT_BLK; c++)
#pragma unroll
        for (int p = 0; p < 4; p++) acc[c][p] = 0.f;

    for (int ci = 0; ci < Cin; ci++) {
        const float* ch = inB + (size_t)ci * HW;
#pragma unroll
        for (int i = 0; i < 5; i++) {
            int idx = tid + i * 256;
            if (idx < 18 * 66) {
                int r = idx / 66, c = idx - (idx / 66) * 66;
                int gy = y0 - 1 + r, gx = x0 - 1 + c;
                float v = 0.f;
                if ((unsigned)gy < H && (unsigned)gx < W) v = ch[gy * W + gx];
                s_in[r][c] = v;
            }
        }
        if (tid < COUT_BLK * 9)
            s_w[tid] = w[((size_t)(g * COUT_BLK + tid / 9) * Cin + ci) * 9 + tid % 9];
        __syncthreads();

        float r0[6], r1[6], r2[6];
#pragma unroll
        for (int k = 0; k < 6; k++) {
            r0[k] = s_in[ty][tx * 4 + k];
            r1[k] = s_in[ty + 1][tx * 4 + k];
            r2[k] = s_in[ty + 2][tx * 4 + k];
        }
#pragma unroll
        for (int co = 0; co < COUT_BLK; co++) {
            float w0 = s_w[co * 9 + 0], w1v = s_w[co * 9 + 1], w2v = s_w[co * 9 + 2];
            float w3v = s_w[co * 9 + 3], w4v = s_w[co * 9 + 4], w5v = s_w[co * 9 + 5];
            float w6v = s_w[co * 9 + 6], w7v = s_w[co * 9 + 7], w8v = s_w[co * 9 + 8];
#pragma unroll
            for (int p = 0; p < 4; p++) {
                float s = acc[co][p];
                s += w0  * r0[p]; s += w1v * r0[p + 1]; s += w2v * r0[p + 2];
                s += w3v * r1[p]; s += w4v * r1[p + 1]; s += w5v * r1[p + 2];
                s += w6v * r2[p]; s += w7v * r2[p + 1]; s += w8v * r2[p + 2];
                acc[co][p] = s;
            }
        }
        __syncthreads();
    }

#pragma unroll
    for (int co = 0; co < COUT_BLK; co++) {
        float bi = bias[g * COUT_BLK + co];
        float* o = out + (size_t)b * outStride + (size_t)(g * COUT_BLK + co) * HW
                 + (y0 + ty) * W + x0 + tx * 4;
#pragma unroll
        for (int p = 0; p < 4; p++) {
            float v = acc[co][p] + bi;
            o[p] = (v >= 0.f) ? v : 0.1f * v;
        }
    }
}

// ---------------------------------------------------------------------------
// conv_mma4: half-row tiles (N = 64), 1-term pure fp16 (w_h · x_h).
// ---------------------------------------------------------------------------
template <int Cin, int Cout, int THREADS, int MINB>
__global__ __launch_bounds__(THREADS, MINB) void conv_mma4_kernel(
    const uint32_t* __restrict__ inBase,
    const uint4* __restrict__ Apack,
    const float* __restrict__ bias,
    float* __restrict__ outBase,
    uint32_t* __restrict__ outHalfBase)
{
    constexpr int nC  = (Cin + 15) / 16;
    constexpr int MFT = Cout / 16;
    constexpr int SR  = 72;
    constexpr int BUF = 16 * 3 * SR;

    __shared__ uint32_t raw[2 * BUF];
    const int tid = threadIdx.x, lane = tid & 31, wrp = tid >> 5;
    const int wm0 = wrp * 32;
    const int y  = blockIdx.x >> 1;
    const int x0 = (blockIdx.x & 1) << 6;
    const int b  = blockIdx.y;
    const uint32_t* inB = inBase + (size_t)b * FEAT_STRIDE;
    const uint32_t rawAddr = smem_u32(raw);
    const uint4* apw = Apack + (size_t)(wrp * 2) * 32 + lane;

    float acc[2][8][4];
#pragma unroll
    for (int mi = 0; mi < 2; mi++)
#pragma unroll
        for (int nf = 0; nf < 8; nf++)
#pragma unroll
            for (int p = 0; p < 4; p++) acc[mi][nf][p] = 0.f;

    auto stage = [&](int kt, int bufsel) {
        for (int i = tid; i < 768; i += THREADS) {
            int c = i / 48;
            int rem = i - c * 48;
            int r = rem >> 4, v = rem & 15;
            int ci = kt * 16 + c;
            int yr = y + r - 1;
            uint32_t foff = (uint32_t)(bufsel * BUF + (c * 3 + r) * SR + 4 + v * 4);
            if (ci < Cin && (unsigned)yr < (unsigned)H)
                cp_async16(rawAddr + foff * 4, inB + (size_t)ci * HW + yr * W + x0 + v * 4);
            else
                *(uint4*)(raw + foff) = make_uint4(0u, 0u, 0u, 0u);
        }
        for (int i = tid; i < 96; i += THREADS) {
            int c = i / 6;
            int rem = i - c * 6;
            int r = rem >> 1, s = rem & 1;
            int ci = kt * 16 + c;
            int yr = y + r - 1;
            int x = s ? (x0 + 64) : (x0 - 1);
            uint32_t foff = (uint32_t)(bufsel * BUF + (c * 3 + r) * SR + (s ? 68 : 3));
            if (ci < Cin && (unsigned)yr < (unsigned)H && (unsigned)x < (unsigned)W)
                cp_async4(rawAddr + foff * 4, inB + (size_t)ci * HW + yr * W + x);
            else
                raw[foff] = 0u;
        }
    };

    stage(0, 0);
    CP_COMMIT();

    const int t = lane & 3;
    const int nbase = (lane >> 2) + 3;

    uint4 ah0, ah1;
    { const uint4* p = apw; ah0 = p[0]; ah1 = p[32]; }

    for (int kt = 0; kt < nC; kt++) {
        const int buf = kt & 1;
        if (kt + 1 < nC) {
            stage(kt + 1, buf ^ 1);
            CP_COMMIT();
            CP_WAIT1();
        } else {
            CP_WAIT0();
        }
        __syncthreads();

        const uint32_t* rb = raw + buf * BUF;

#pragma unroll
        for (int ks = 0; ks < 9; ks++) {
            uint4 nh0, nh1;
            {
                int nkt = kt, nks = ks + 1;
                if (nks == 9) { nkt = kt + 1; nks = 0; }
                if (nkt < nC) {
                    const uint4* p = apw + (size_t)((nkt * 9 + nks) * MFT) * 32;
                    nh0 = p[0]; nh1 = p[32];
                } else {
                    nh0 = nh1 = make_uint4(0u, 0u, 0u, 0u);
                }
            }

            int j0 = ks * 16 + 2 * t, j1 = j0 + 8;
            const uint32_t* q0;
            const uint32_t* q1;
            const uint32_t* q2;
            const uint32_t* q3;
            {
                int c = j0 / 9, tp = j0 - c * 9;
                q0 = rb + (c * 3 + tp / 3) * SR + (tp % 3) + nbase;
            }
            {
                int jj = j0 + 1;
                int c = jj / 9, tp = jj - c * 9;
                q1 = rb + (c * 3 + tp / 3) * SR + (tp % 3) + nbase;
            }
            {
                int c = j1 / 9, tp = j1 - c * 9;
                q2 = rb + (c * 3 + tp / 3) * SR + (tp % 3) + nbase;
            }
            {
                int jj = j1 + 1;
                int c = jj / 9, tp = jj - c * 9;
                q3 = rb + (c * 3 + tp / 3) * SR + (tp % 3) + nbase;
            }

#pragma unroll
            for (int nf = 0; nf < 8; nf += 2) {
                uint32_t a00 = q0[nf * 8],     a01 = q1[nf * 8];
                uint32_t a10 = q2[nf * 8],     a11 = q3[nf * 8];
                uint32_t c00 = q0[nf * 8 + 8], c01 = q1[nf * 8 + 8];
                uint32_t c10 = q2[nf * 8 + 8], c11 = q3[nf * 8 + 8];
                uint32_t bhA0 = __byte_perm(a00, a01, 0x5410);
                uint32_t bhA1 = __byte_perm(a10, a11, 0x5410);
                uint32_t bhB0 = __byte_perm(c00, c01, 0x5410);
                uint32_t bhB1 = __byte_perm(c10, c11, 0x5410);
                MMA_F16(acc[0][nf],     ah0.x, ah0.y, ah0.z, ah0.w, bhA0, bhA1);
                MMA_F16(acc[1][nf],     ah1.x, ah1.y, ah1.z, ah1.w, bhA0, bhA1);
                MMA_F16(acc[0][nf + 1], ah0.x, ah0.y, ah0.z, ah0.w, bhB0, bhB1);
                MMA_F16(acc[1][nf + 1], ah1.x, ah1.y, ah1.z, ah1.w, bhB0, bhB1);
            }
            ah0 = nh0; ah1 = nh1;
        }
        __syncthreads();
    }

    const int q = lane & 3, g2 = lane >> 2;
    float* outB = outBase + (size_t)b * FEAT_STRIDE;
    uint32_t* outH = outHalfBase + (size_t)b * FEAT_STRIDE;
#pragma unroll
    for (int mi = 0; mi < 2; mi++) {
        int m0 = wm0 + mi * 16 + g2;
        float bLo = __ldg(bias + m0), bHi = __ldg(bias + m0 + 8);
        float* o0 = outB + (size_t)m0 * HW;
        float* o1 = o0 + 8 * HW;
        uint32_t* h0 = outH + (size_t)m0 * HW;
        uint32_t* h1 = h0 + 8 * HW;
#pragma unroll
        for (int nf = 0; nf < 8; nf++) {
            int off = y * W + x0 + nf * 8 + 2 * q;
            float v0 = acc[mi][nf][0] + bLo, v1 = acc[mi][nf][1] + bLo;
            float v2 = acc[mi][nf][2] + bHi, v3 = acc[mi][nf][3] + bHi;
            v0 = (v0 >= 0.f) ? v0 : 0.1f * v0;
            v1 = (v1 >= 0.f) ? v1 : 0.1f * v1;
            v2 = (v2 >= 0.f) ? v2 : 0.1f * v2;
            v3 = (v3 >= 0.f) ? v3 : 0.1f * v3;
            *(float2*)(o0 + off) = make_float2(v0, v1);
            *(float2*)(o1 + off) = make_float2(v2, v3);
            *(uint2*)(h0 + off) = make_uint2(packhl(v0), packhl(v1));
            *(uint2*)(h1 + off) = make_uint2(packhl(v2), packhl(v3));
        }
    }
}

// ---------------------------------------------------------------------------
// conv_mma3: full-row kernel (s4/s5), 1-term pure fp16
// ---------------------------------------------------------------------------
template <int Cin, int Cout, int NW, int NROWS, int THREADS, int MINB>
__global__ __launch_bounds__(THREADS, MINB) void conv_mma3_kernel(
    const uint32_t* __restrict__ inBase,
    const uint4* __restrict__ Apack,
    const float* __restrict__ bias,
    float* __restrict__ outBase,
    uint32_t* __restrict__ outHalfBase)
{
    constexpr int nC    = (Cin + 15) / 16;
    constexpr int R     = NROWS + 2;
    constexpr int SROW  = 136;
    constexpr int BUFSZ = 16 * R * SROW;
    constexpr int MFT   = Cout / 16;

    extern __shared__ uint32_t raw[];
    const int tid = threadIdx.x, lane = tid & 31, wrp = tid >> 5;
    const int wm = wrp / NW, wn = wrp % NW;
    const int wm0 = wm * 32, wn0 = wn * 64;
    const int wrow = wn0 >> 7, wcol = wn0 & 127;
    const int yBase = blockIdx.x * NROWS, b = blockIdx.y;
    const uint32_t* inB = inBase + (size_t)b * FEAT_STRIDE;
    const uint32_t rawAddr = smem_u32(raw);

    const uint4* apw = Apack + (size_t)(wm * 2) * 32 + lane;

    for (int i = tid; i < 2 * 16 * R; i += THREADS) {
        raw[i * SROW + 3]   = 0u;
        raw[i * SROW + 132] = 0u;
    }

    float acc[2][8][4];
#pragma unroll
    for (int mi = 0; mi < 2; mi++)
#pragma unroll
        for (int ni = 0; ni < 8; ni++)
#pragma unroll
            for (int p = 0; p < 4; p++) acc[mi][ni][p] = 0.f;

    auto stage = [&](int kt, int bufsel) {
        const int total = 16 * R * 32;
        for (int i = tid; i < total; i += THREADS) {
            int c   = i / (R * 32);
            int rem = i - c * (R * 32);
            int rr  = rem >> 5, v = rem & 31;
            int ci  = kt * 16 + c;
            int gy  = yBase + rr - 1;
            int foff = bufsel * BUFSZ + (c * R + rr) * SROW + 4 + v * 4;
            if (ci < Cin && (unsigned)gy < (unsigned)H) {
                cp_async16(rawAddr + (uint32_t)(foff * 4),
                           inB + (size_t)ci * HW + gy * W + v * 4);
            } else {
                *(uint4*)(raw + foff) = make_uint4(0u, 0u, 0u, 0u);
            }
        }
    };

    stage(0, 0);
    CP_COMMIT();

    const int t = lane & 3;
    const int nbase = wcol + (lane >> 2);

    uint4 ah0, ah1;
    {
        const uint4* p = apw;
        ah0 = p[0]; ah1 = p[32];
    }

    for (int kt = 0; kt < nC; kt++) {
        const int buf = kt & 1;
        if (kt + 1 < nC) {
            stage(kt + 1, buf ^ 1);
            CP_COMMIT();
            CP_WAIT1();
        } else {
            CP_WAIT0();
        }
        __syncthreads();

        const uint32_t* rb = raw + buf * BUFSZ;

#pragma unroll
        for (int ks = 0; ks < 9; ks++) {
            uint4 nh0, nh1;
            {
                int nkt = kt, nks = ks + 1;
                if (nks == 9) { nkt = kt + 1; nks = 0; }
                if (nkt < nC) {
                    const uint4* p = apw + (size_t)((nkt * 9 + nks) * MFT) * 32;
                    nh0 = p[0]; nh1 = p[32];
                } else {
                    nh0 = nh1 = make_uint4(0u, 0u, 0u, 0u);
                }
            }

            int j0 = ks * 16 + 2 * t, j1 = j0 + 8;
            const uint32_t* q0;
            const uint32_t* q1;
            const uint32_t* q2;
            const uint32_t* q3;
            {
                int c = j0 / 9, tp = j0 - c * 9;
                q0 = rb + (c * R + wrow + tp / 3) * SROW + (tp % 3) + 3 + nbase;
            }
            {
                int jj = j0 + 1;
                int c = jj / 9, tp = jj - c * 9;
                q1 = rb + (c * R + wrow + tp / 3) * SROW + (tp % 3) + 3 + nbase;
            }
            {
                int c = j1 / 9, tp = j1 - c * 9;
                q2 = rb + (c * R + wrow + tp / 3) * SROW + (tp % 3) + 3 + nbase;
            }
            {
                int jj = j1 + 1;
                int c = jj / 9, tp = jj - c * 9;
                q3 = rb + (c * R + wrow + tp / 3) * SROW + (tp % 3) + 3 + nbase;
            }

#pragma unroll
            for (int nf = 0; nf < 8; nf++) {
                uint32_t w00 = q0[nf * 8], w01 = q1[nf * 8];
                uint32_t w10 = q2[nf * 8], w11 = q3[nf * 8];
                uint32_t bh0 = __byte_perm(w00, w01, 0x5410);
                uint32_t bh1 = __byte_perm(w10, w11, 0x5410);
                MMA_F16(acc[0][nf], ah0.x, ah0.y, ah0.z, ah0.w, bh0, bh1);
                MMA_F16(acc[1][nf], ah1.x, ah1.y, ah1.z, ah1.w, bh0, bh1);
            }
            ah0 = nh0; ah1 = nh1;
        }
        __syncthreads();
    }

    const int q = lane & 3, g2 = lane >> 2;
    float* outB = outBase + (size_t)b * FEAT_STRIDE;
    uint32_t* outH = outHalfBase + (size_t)b * FEAT_STRIDE;
#pragma unroll
    for (int mi = 0; mi < 2; mi++) {
        int m0 = wm0 + mi * 16 + g2;
        float bLo = __ldg(bias + m0), bHi = __ldg(bias + m0 + 8);
        float* o0 = outB + (size_t)m0 * HW;
        float* o1 = o0 + 8 * HW;
        uint32_t* h0 = outH + (size_t)m0 * HW;
        uint32_t* h1 = h0 + 8 * HW;
#pragma unroll
        for (int ni = 0; ni < 8; ni++) {
            int n = wn0 + ni * 8 + 2 * q;
            int off = (yBase + (n >> 7)) * W + (n & 127);
            float v0 = acc[mi][ni][0] + bLo, v1 = acc[mi][ni][1] + bLo;
            float v2 = acc[mi][ni][2] + bHi, v3 = acc[mi][ni][3] + bHi;
            v0 = (v0 >= 0.f) ? v0 : 0.1f * v0;
            v1 = (v1 >= 0.f) ? v1 : 0.1f * v1;
            v2 = (v2 >= 0.f) ? v2 : 0.1f * v2;
            v3 = (v3 >= 0.f) ? v3 : 0.1f * v3;
            *(float2*)(o0 + off) = make_float2(v0, v1);
            *(float2*)(o1 + off) = make_float2(v2, v3);
            *(uint2*)(h0 + off) = make_uint2(packhl(v0), packhl(v1));
            *(uint2*)(h1 + off) = make_uint2(packhl(v2), packhl(v3));
        }
    }
}

// ---------------------------------------------------------------------------
// Launch
// ---------------------------------------------------------------------------
extern "C" void kernel_launch(void* const* d_in, const int* in_sizes, int n_in,
                              void* d_out, int out_size)
{
    (void)in_sizes; (void)n_in; (void)out_size;
    const float* tenOne    = (const float*)d_in[0];
    const float* tenTwo    = (const float*)d_in[1];
    const float* prev_flow = (const float*)d_in[2];
    const float* prev_feat = (const float*)d_in[3];
    const float* w_upflow  = (const float*)d_in[4];
    const float* b_upflow  = (const float*)d_in[5];
    const float* w_upfeat  = (const float*)d_in[6];
    const float* b_upfeat  = (const float*)d_in[7];
    const float* w1 = (const float*)d_in[8];   const float* b1 = (const float*)d_in[9];
    const float* w2 = (const float*)d_in[10];  const float* b2 = (const float*)d_in[11];
    const float* w3 = (const float*)d_in[12];  const float* b3 = (const float*)d_in[13];
    const float* w4 = (const float*)d_in[14];  const float* b4 = (const float*)d_in[15];
    const float* w5 = (const float*)d_in[16];  const float* b5 = (const float*)d_in[17];
    const float* w6 = (const float*)d_in[18];  const float* b6 = (const float*)d_in[19];

    float* flow = (float*)d_out;
    float* feat = flow + (size_t)Bn * 2 * HW;

    uint32_t* apack;
    cudaGetSymbolAddress((void**)&apack, g_Apack);
    uint32_t* half;
    cudaGetSymbolAddress((void**)&half, g_half);

    const int SMA = 52224, SMB = 69632;
    cudaFuncSetAttribute(conv_mma3_kernel<533, 64, 2, 1, 128, 3>, cudaFuncAttributeMaxDynamicSharedMemorySize, SMA);
    cudaFuncSetAttribute(conv_mma3_kernel<597, 32, 4, 2, 128, 3>, cudaFuncAttributeMaxDynamicSharedMemorySize, SMB);

    const int NPIX = Bn * HW;

    pack_all_kernel<<<(APACK_TOTAL + 255) / 256, 256>>>(w1, w2, w3, w4, w5, apack);
    upconv_both_kernel<<<dim3((NPIX + 255) / 256, 2), 256>>>(
        prev_flow, w_upflow, b_upflow, prev_feat, w_upfeat, b_upfeat, feat);
    {
        size_t n4 = (size_t)Bn * C1CH * HW / 4;
        copy_t1_kernel<<<(unsigned)((n4 + 255) / 256), 256>>>(tenOne, feat);
    }
    warp_kernel<<<(NPIX + 255) / 256, 256>>>(tenTwo, feat);
    corr_kernel<<<dim3(W / 32, H / 4, Bn), 128>>>(tenOne, feat);

    // fp16 1-term mma conv tower
    conv_mma4_kernel<181, 128, 128, 4><<<dim3(128, Bn), 128>>>(
        half + (size_t)OFF_VOL * HW, (const uint4*)(apack + APACK_OFF1), b1,
        feat + (size_t)OFF_C1 * HW, half + (size_t)OFF_C1 * HW);
    conv_mma4_kernel<309, 128, 128, 4><<<dim3(128, Bn), 128>>>(
        half + (size_t)OFF_C1 * HW, (const uint4*)(apack + APACK_OFF2), b2,
        feat + (size_t)OFF_C2 * HW, half + (size_t)OFF_C2 * HW);
    conv_mma4_kernel<437, 96, 96, 5><<<dim3(128, Bn), 96>>>(
        half + (size_t)OFF_C2 * HW, (const uint4*)(apack + APACK_OFF3), b3,
        feat + (size_t)OFF_C3 * HW, half + (size_t)OFF_C3 * HW);
    conv_mma3_kernel<533, 64, 2, 1, 128, 3><<<dim3(64, Bn), 128, SMA>>>(
        half + (size_t)OFF_C3 * HW, (const uint4*)(apack + APACK_OFF4), b4,
        feat + (size_t)OFF_C4 * HW, half + (size_t)OFF_C4 * HW);
    conv_mma3_kernel<597, 32, 4, 2, 128, 3><<<dim3(32, Bn), 128, SMB>>>(
        half + (size_t)OFF_C4 * HW, (const uint4*)(apack + APACK_OFF5), b5,
        feat + (size_t)OFF_C5 * HW, half + (size_t)OFF_C5 * HW);

    // conv6 (Cout=2) -> flow, FFMA path
    conv3x3_kernel<2><<<dim3(1, 8, Bn), 256>>>(
        feat + (size_t)OFF_C5 * HW, w6, b6, flow,
        629, FEAT_STRIDE, 2 * HW);
}

// round 14
// speedup vs baseline: 2.0452x; 1.4272x over previous
#include <cuda_runtime.h>
#include <cuda_fp16.h>
#include <math.h>
#include <stdint.h>

// ---------------------------------------------------------------------------
#define Bn 8
#define H 64
#define W 128
#define HW (H * W)
#define C1CH 96
#define HIN 32
#define WIN 64
#define HWIN (HIN * WIN)
#define PREVC 661

#define FEAT_C 629
#define FEAT_STRIDE (FEAT_C * HW)

// [c5(32) | c4(64) | c3(96) | c2(128) | c1(128) | vol(81) | tenOne(96) | flow(2) | upfeat(2)]
#define OFF_C5   0
#define OFF_C4   32
#define OFF_C3   96
#define OFF_C2   192
#define OFF_C1   320
#define OFF_VOL  448
#define OFF_T1   529
#define OFF_FLOW 625
#define OFF_UPF  627

#define NPAIRS 315                 // ceil(630/2); channel 629 is a dummy
#define HALF_B ((size_t)NPAIRS * HW)   // u32 per batch in g_half

__device__ float g_warped[(size_t)Bn * C1CH * HW];

// channel-pair-interleaved fp16 shadow: u32[b][pair][pix] = half2(ch 2p, ch 2p+1)
__device__ uint32_t g_half[(size_t)Bn * NPAIRS * HW];

// fp16 A-fragments, chunk = 144 k; k-order: tap-major (ks=tap), channel-minor
#define APACK_OFF1 0
#define APACK_OFF2 110592      // + 12*9*8*128
#define APACK_OFF3 294912      // + 20*9*8*128
#define APACK_OFF4 488448      // + 28*9*6*128
#define APACK_OFF5 645120      // + 34*9*4*128
#define APACK_TOTAL 732672     // + 38*9*2*128
__device__ uint32_t g_Apack[APACK_TOTAL];

// per-parity packed upconv weights: [parity 4][ci 663][8 floats]
__device__ float g_upw[4 * 663 * 8];

// ---------------------------------------------------------------------------
__device__ __forceinline__ uint32_t smem_u32(const void* p) {
    uint32_t a;
    asm("{ .reg .u64 t; cvta.to.shared.u64 t, %1; cvt.u32.u64 %0, t; }" : "=r"(a) : "l"(p));
    return a;
}
__device__ __forceinline__ void cp_async16(uint32_t dst, const void* src) {
    asm volatile("cp.async.ca.shared.global [%0], [%1], 16;" :: "r"(dst), "l"(src));
}
__device__ __forceinline__ void cp_async4(uint32_t dst, const void* src) {
    asm volatile("cp.async.ca.shared.global [%0], [%1], 4;" :: "r"(dst), "l"(src));
}
#define CP_COMMIT() asm volatile("cp.async.commit_group;")
#define CP_WAIT0()  asm volatile("cp.async.wait_group 0;")
#define CP_WAIT1()  asm volatile("cp.async.wait_group 1;")

__device__ __forceinline__ void st_half(int b, int ch, int pix, float v) {
    __half* hp = (__half*)(g_half + (size_t)b * HALF_B);
    hp[((size_t)(ch >> 1) * HW + pix) * 2 + (ch & 1)] = __float2half_rn(v);
}

#define MMA_F16(c, a0, a1, a2, a3, b0v, b1v) \
    asm volatile( \
        "mma.sync.aligned.m16n8k16.row.col.f32.f16.f16.f32 " \
        "{%0,%1,%2,%3}, {%4,%5,%6,%7}, {%8,%9}, {%0,%1,%2,%3};" \
        : "+f"((c)[0]), "+f"((c)[1]), "+f"((c)[2]), "+f"((c)[3]) \
        : "r"(a0), "r"(a1), "r"(a2), "r"(a3), \
          "r"(b0v), "r"(b1v))

// ---------------------------------------------------------------------------
// Weight pre-pack: k-order tap-major.  u32 idx = (((kt*9+ks)*MFT+mf)*32+lane)*4+reg
//   m  = mf*16 + (lane>>2) + 8*(reg&1)
//   ch = kt*16 + (lane&3)*2 + 8*(reg>>1) + {0,1};  tap = ks
// ---------------------------------------------------------------------------
__device__ __forceinline__ void pack_one(const float* w, uint32_t* dst, int idx,
                                         int Cin, int Cout)
{
    int MFT = Cout >> 4;
    int reg = idx & 3, lane = (idx >> 2) & 31;
    int u = idx >> 7;
    int mf = u % MFT;
    int v3 = u / MFT;
    int ks = v3 % 9, kt = v3 / 9;
    int m = mf * 16 + (lane >> 2) + 8 * (reg & 1);
    int ch = kt * 16 + (lane & 3) * 2 + 8 * (reg >> 1);
    float v0 = (ch     < Cin) ? w[((size_t)m * Cin + ch)     * 9 + ks] : 0.f;
    float v1 = (ch + 1 < Cin) ? w[((size_t)m * Cin + ch + 1) * 9 + ks] : 0.f;
    __half h0 = __float2half_rn(v0), h1 = __float2half_rn(v1);
    dst[idx] = (uint32_t)__half_as_ushort(h0) | ((uint32_t)__half_as_ushort(h1) << 16);
}

__global__ void pack_all_kernel(const float* __restrict__ w1, const float* __restrict__ w2,
                                const float* __restrict__ w3, const float* __restrict__ w4,
                                const float* __restrict__ w5, uint32_t* __restrict__ dst)
{
    int idx = blockIdx.x * blockDim.x + threadIdx.x;
    if (idx >= APACK_TOTAL) return;
    if      (idx < APACK_OFF2) pack_one(w1, dst + APACK_OFF1, idx - APACK_OFF1, 181, 128);
    else if (idx < APACK_OFF3) pack_one(w2, dst + APACK_OFF2, idx - APACK_OFF2, 309, 128);
    else if (idx < APACK_OFF4) pack_one(w3, dst + APACK_OFF3, idx - APACK_OFF3, 437, 96);
    else if (idx < APACK_OFF5) pack_one(w4, dst + APACK_OFF4, idx - APACK_OFF4, 533, 64);
    else                       pack_one(w5, dst + APACK_OFF5, idx - APACK_OFF5, 597, 32);
}

// per-parity upconv weight pack: [parity][ci_all(663)][8]
// ci_all 0..1 -> upflow; 2..662 -> upfeat channel ci_all-2
__global__ void pack_upw_kernel(const float* __restrict__ wF, const float* __restrict__ wU,
                                float* __restrict__ dst)
{
    int idx = blockIdx.x * blockDim.x + threadIdx.x;
    if (idx >= 4 * 663 * 8) return;
    int j = idx & 7;
    int q = idx >> 3;
    int ci_all = q % 663, parity = q / 663;
    int py = parity >> 1, px = parity & 1;
    int ky0 = 1 + py, ky1 = py ? 0 : 3;
    int kx0 = 1 + px, kx1 = px ? 0 : 3;
    int cout = j >> 2, tp = j & 3;
    int ky = (tp < 2) ? ky0 : ky1;
    int kx = (tp & 1) ? kx1 : kx0;
    const float* src;
    int ci;
    if (ci_all < 2) { src = wF; ci = ci_all; }
    else            { src = wU; ci = ci_all - 2; }
    dst[idx] = src[(size_t)ci * 32 + cout * 16 + ky * 4 + kx];
}

// ---------------------------------------------------------------------------
// Merged ConvTranspose2d(k=4,s=2,p=1), Cout=2, packed parity weights.
// ---------------------------------------------------------------------------
__global__ void upconv_both_kernel(const float* __restrict__ inF,
                                   const float* __restrict__ bF,
                                   const float* __restrict__ inU,
                                   const float* __restrict__ bU,
                                   float* __restrict__ feat)
{
    int gid = blockIdx.x * blockDim.x + threadIdx.x;
    if (gid >= Bn * HW) return;
    const int which = blockIdx.y;
    const float* in  = which ? inU : inF;
    const float* bias= which ? bU  : bF;
    const int Cin    = which ? PREVC : 2;
    const int choff  = which ? OFF_UPF : OFF_FLOW;

    int b = gid / HW;
    int pix = gid - b * HW;
    int y = pix / W, x = pix - (pix / W) * W;

    int iy0 = y >> 1;
    int iy1 = (y >> 1) + ((y & 1) ? 1 : -1);
    int ix0 = x >> 1;
    int ix1 = (x >> 1) + ((x & 1) ? 1 : -1);
    bool vy1 = (unsigned)iy1 < HIN;
    bool vx1 = (unsigned)ix1 < WIN;

    int parity = (y & 1) * 2 + (x & 1);
    const float* wbase = g_upw + (size_t)parity * (663 * 8) + (which ? 16 : 0);

    float a0 = bias[0], a1 = bias[1];
    const float* pin = in + (size_t)b * Cin * HWIN;
    int p00 = iy0 * WIN + ix0, p01 = iy0 * WIN + ix1;
    int p10 = iy1 * WIN + ix0, p11 = iy1 * WIN + ix1;

    for (int ci = 0; ci < Cin; ci++) {
        const float* p = pin + (size_t)ci * HWIN;
        float4 f0 = *(const float4*)(wbase + (size_t)ci * 8);
        float4 f1 = *(const float4*)(wbase + (size_t)ci * 8 + 4);
        float u0 = p[p00];
        float u1 = vx1 ? p[p01] : 0.f;
        float u2 = vy1 ? p[p10] : 0.f;
        float u3 = (vy1 && vx1) ? p[p11] : 0.f;
        a0 += u0 * f0.x + u1 * f0.y + u2 * f0.z + u3 * f0.w;
        a1 += u0 * f1.x + u1 * f1.y + u2 * f1.z + u3 * f1.w;
    }
    size_t o = (size_t)b * FEAT_STRIDE + (size_t)choff * HW + pix;
    feat[o]      = a0;
    feat[o + HW] = a1;
    st_half(b, choff,     pix, a0);
    st_half(b, choff + 1, pix, a1);
}

__global__ void copy_t1_kernel(const float* __restrict__ t1, float* __restrict__ feat)
{
    size_t i = (size_t)blockIdx.x * blockDim.x + threadIdx.x;
    const size_t n4 = (size_t)Bn * C1CH * HW / 4;
    if (i >= n4) return;
    const size_t per = (size_t)C1CH * HW / 4;
    size_t b = i / per, r = i - b * per;
    int ch = OFF_T1 + (int)(r / (HW / 4));
    int pix = (int)(r % (HW / 4)) * 4;
    float4 v = ((const float4*)t1)[i];
    size_t o = b * (size_t)FEAT_STRIDE + (size_t)OFF_T1 * HW;
    ((float4*)(feat + o))[r] = v;
    st_half((int)b, ch, pix,     v.x);
    st_half((int)b, ch, pix + 1, v.y);
    st_half((int)b, ch, pix + 2, v.z);
    st_half((int)b, ch, pix + 3, v.w);
}

__global__ void warp_kernel(const float* __restrict__ tenTwo, const float* __restrict__ feat)
{
    int gid = blockIdx.x * blockDim.x + threadIdx.x;
    if (gid >= Bn * HW) return;
    int b = gid / HW;
    int pix = gid - b * HW;
    int y = pix / W, x = pix - (pix / W) * W;

    const float* fl = feat + (size_t)b * FEAT_STRIDE + (size_t)OFF_FLOW * HW + pix;
    float px = (float)x + fl[0]  * 1.25f;
    float py = (float)y + fl[HW] * 1.25f;
    float fx = floorf(px), fy = floorf(py);
    float wx = px - fx, wy = py - fy;
    int ix0 = (int)fx, iy0 = (int)fy;
    int ix1 = ix0 + 1, iy1 = iy0 + 1;
    bool vx0 = (unsigned)ix0 < W, vx1 = (unsigned)ix1 < W;
    bool vy0 = (unsigned)iy0 < H, vy1 = (unsigned)iy1 < H;
    float w00 = (1.f - wy) * (1.f - wx), w01 = (1.f - wy) * wx;
    float w10 = wy * (1.f - wx),         w11 = wy * wx;
    int o00 = iy0 * W + ix0, o01 = iy0 * W + ix1;
    int o10 = iy1 * W + ix0, o11 = iy1 * W + ix1;

    const float* t = tenTwo + (size_t)b * C1CH * HW;
    float* o = g_warped + (size_t)b * C1CH * HW + pix;
    for (int c = 0; c < C1CH; c++) {
        const float* tc = t + (size_t)c * HW;
        float v = 0.f;
        if (vy0 && vx0) v += tc[o00] * w00;
        if (vy0 && vx1) v += tc[o01] * w01;
        if (vy1 && vx0) v += tc[o10] * w10;
        if (vy1 && vx1) v += tc[o11] * w11;
        o[(size_t)c * HW] = v;
    }
}

__global__ __launch_bounds__(128) void corr_kernel(const float* __restrict__ tenOne,
                                                   float* __restrict__ feat)
{
    __shared__ float s_f1[4][32];
    __shared__ float s_w2[12][40];
    int tid = threadIdx.x;
    int tx = tid & 31, ty = tid >> 5;
    int x0 = blockIdx.x * 32, y0 = blockIdx.y * 4, b = blockIdx.z;

    float acc[81];
#pragma unroll
    for (int d = 0; d < 81; d++) acc[d] = 0.f;

    const float* f1 = tenOne + (size_t)b * C1CH * HW;
    const float* f2 = g_warped + (size_t)b * C1CH * HW;

    for (int c = 0; c < C1CH; c++) {
        const float* f1c = f1 + (size_t)c * HW;
        const float* f2c = f2 + (size_t)c * HW;
        __syncthreads();
        s_f1[ty][tx] = f1c[(y0 + ty) * W + x0 + tx];
#pragma unroll
        for (int i = 0; i < 4; i++) {
            int idx = tid + i * 128;
            if (idx < 480) {
                int r = idx / 40, cc = idx - (idx / 40) * 40;
                int gy = y0 - 4 + r, gx = x0 - 4 + cc;
                float v = 0.f;
                if ((unsigned)gy < H && (unsigned)gx < W) v = f2c[gy * W + gx];
                s_w2[r][cc] = v;
            }
        }
        __syncthreads();
        float a = s_f1[ty][tx];
#pragma unroll
        for (int dy = 0; dy < 9; dy++)
#pragma unroll
            for (int dx = 0; dx < 9; dx++)
                acc[dy * 9 + dx] += a * s_w2[ty + dy][tx + dx];
    }

    int pix = (y0 + ty) * W + x0 + tx;
    size_t obase = (size_t)b * FEAT_STRIDE + (size_t)OFF_VOL * HW + pix;
    const float inv = 1.f / 96.f;
#pragma unroll
    for (int d = 0; d < 81; d++) {
        float v = acc[d] * inv;
        v = (v >= 0.f) ? v : 0.1f * v;
        feat[obase + (size_t)d * HW] = v;
        st_half(b, OFF_VOL + d, pix, v);
    }
}

// ---------------------------------------------------------------------------
// FFMA direct 3x3 conv (conv6, Cout=2)
// ---------------------------------------------------------------------------
template <int COUT_BLK>
__global__ __launch_bounds__(256) void conv3x3_kernel(
    const float* __restrict__ in, const float* __restrict__ w,
    const float* __restrict__ bias, float* __restrict__ out,
    int Cin, int inStride, int outStride)
{
    __shared__ float s_in[18][66];
    __shared__ float s_w[COUT_BLK * 9];
    const int tid = threadIdx.x;
    const int tx = tid & 15, ty = tid >> 4;
    const int g = blockIdx.x;
    const int tileX = blockIdx.y & 1, tileY = blockIdx.y >> 1;
    const int b = blockIdx.z;
    const int x0 = tileX * 64, y0 = tileY * 16;

    const float* inB = in + (size_t)b * inStride;
    float acc[COUT_BLK][4];
#pragma unroll
    for (int c = 0; c < COUT_BLK; c++)
#pragma unroll
        for (int p = 0; p < 4; p++) acc[c][p] = 0.f;

    for (int ci = 0; ci < Cin; ci++) {
        const float* ch = inB + (size_t)ci * HW;
#pragma unroll
        for (int i = 0; i < 5; i++) {
            int idx = tid + i * 256;
            if (idx < 18 * 66) {
                int r = idx / 66, c = idx - (idx / 66) * 66;
                int gy = y0 - 1 + r, gx = x0 - 1 + c;
                float v = 0.f;
                if ((unsigned)gy < H && (unsigned)gx < W) v = ch[gy * W + gx];
                s_in[r][c] = v;
            }
        }
        if (tid < COUT_BLK * 9)
            s_w[tid] = w[((size_t)(g * COUT_BLK + tid / 9) * Cin + ci) * 9 + tid % 9];
        __syncthreads();

        float r0[6], r1[6], r2[6];
#pragma unroll
        for (int k = 0; k < 6; k++) {
            r0[k] = s_in[ty][tx * 4 + k];
            r1[k] = s_in[ty + 1][tx * 4 + k];
            r2[k] = s_in[ty + 2][tx * 4 + k];
        }
#pragma unroll
        for (int co = 0; co < COUT_BLK; co++) {
            float w0 = s_w[co * 9 + 0], w1v = s_w[co * 9 + 1], w2v = s_w[co * 9 + 2];
            float w3v = s_w[co * 9 + 3], w4v = s_w[co * 9 + 4], w5v = s_w[co * 9 + 5];
            float w6v = s_w[co * 9 + 6], w7v = s_w[co * 9 + 7], w8v = s_w[co * 9 + 8];
#pragma unroll
            for (int p = 0; p < 4; p++) {
                float s = acc[co][p];
                s += w0  * r0[p]; s += w1v * r0[p + 1]; s += w2v * r0[p + 2];
                s += w3v * r1[p]; s += w4v * r1[p + 1]; s += w5v * r1[p + 2];
                s += w6v * r2[p]; s += w7v * r2[p + 1]; s += w8v * r2[p + 2];
                acc[co][p] = s;
            }
        }
        __syncthreads();
    }

#pragma unroll
    for (int co = 0; co < COUT_BLK; co++) {
        float bi = bias[g * COUT_BLK + co];
        float* o = out + (size_t)b * outStride + (size_t)(g * COUT_BLK + co) * HW
                 + (y0 + ty) * W + x0 + tx * 4;
#pragma unroll
        for (int p = 0; p < 4; p++) {
            float v = acc[co][p] + bi;
            o[p] = (v >= 0.f) ? v : 0.1f * v;
        }
    }
}

// ---------------------------------------------------------------------------
// conv_mma5: unified tower kernel. N=64 tile, warps = Cout/32, pure fp16.
// Pair-interleaved B: one LDS per b-register, zero perms, constant tap offsets.
// ---------------------------------------------------------------------------
template <int Cin, int Cout, int THREADS, int MINB>
__global__ __launch_bounds__(THREADS, MINB) void conv_mma5_kernel(
    const uint32_t* __restrict__ inPairBase,   // g_half + stage pair base (b=0)
    const uint4* __restrict__ Apack,
    const float* __restrict__ bias,
    float* __restrict__ outBase,               // feat + stage out offset (b=0)
    uint32_t* __restrict__ outPairBase)        // g_half + out pair base (b=0)
{
    constexpr int nC  = (Cin + 15) / 16;
    constexpr int MFT = Cout / 16;
    constexpr int SR  = 72;               // u32 per pair-row (== 8 mod 32)
    constexpr int BUF = 8 * 3 * SR;       // 1728 u32 per buffer

    __shared__ uint32_t raw[2 * BUF];
    const int tid = threadIdx.x, lane = tid & 31, wrp = tid >> 5;
    const int wm0 = wrp * 32;
    const int y  = blockIdx.x >> 1;
    const int x0 = (blockIdx.x & 1) << 6;
    const int b  = blockIdx.y;
    const uint32_t* inP = inPairBase + (size_t)b * HALF_B;
    const uint32_t rawAddr = smem_u32(raw);
    const uint4* apw = Apack + (size_t)(wrp * 2) * 32 + lane;

    float acc[2][8][4];
#pragma unroll
    for (int mi = 0; mi < 2; mi++)
#pragma unroll
        for (int nf = 0; nf < 8; nf++)
#pragma unroll
            for (int p = 0; p < 4; p++) acc[mi][nf][p] = 0.f;

    auto stage = [&](int kt, int bufsel) {
        // interior: 8 pairs x 3 rows x 16 float4 (64 pixels as half2)
        for (int i = tid; i < 384; i += THREADS) {
            int pl = i / 48;
            int rem = i - pl * 48;
            int r = rem >> 4, v = rem & 15;
            int pg = kt * 8 + pl;
            int yr = y + r - 1;
            uint32_t foff = (uint32_t)(bufsel * BUF + (pl * 3 + r) * SR + 4 + v * 4);
            if (2 * pg < Cin && (unsigned)yr < (unsigned)H)
                cp_async16(rawAddr + foff * 4, inP + (size_t)pg * HW + yr * W + x0 + v * 4);
            else
                *(uint4*)(raw + foff) = make_uint4(0u, 0u, 0u, 0u);
        }
        // edges: 8 pairs x 3 rows x 2 (x0-1 at [3], x0+64 at [68])
        for (int i = tid; i < 48; i += THREADS) {
            int pl = i / 6;
            int rem = i - pl * 6;
            int r = rem >> 1, s = rem & 1;
            int pg = kt * 8 + pl;
            int yr = y + r - 1;
            int x = s ? (x0 + 64) : (x0 - 1);
            uint32_t foff = (uint32_t)(bufsel * BUF + (pl * 3 + r) * SR + (s ? 68 : 3));
            if (2 * pg < Cin && (unsigned)yr < (unsigned)H && (unsigned)x < (unsigned)W)
                cp_async4(rawAddr + foff * 4, inP + (size_t)pg * HW + yr * W + x);
            else
                raw[foff] = 0u;
        }
    };

    stage(0, 0);
    CP_COMMIT();

    const int t = lane & 3;
    const int g = lane >> 2;

    uint4 ah0, ah1;
    { const uint4* p = apw; ah0 = p[0]; ah1 = p[32]; }

    for (int kt = 0; kt < nC; kt++) {
        const int buf = kt & 1;
        if (kt + 1 < nC) {
            stage(kt + 1, buf ^ 1);
            CP_COMMIT();
            CP_WAIT1();
        } else {
            CP_WAIT0();
        }
        __syncthreads();

        const uint32_t* rb = raw + buf * BUF;

#pragma unroll
        for (int ks = 0; ks < 9; ks++) {
            uint4 nh0, nh1;
            {
                int nkt = kt, nks = ks + 1;
                if (nks == 9) { nkt = kt + 1; nks = 0; }
                if (nkt < nC) {
                    const uint4* p = apw + (size_t)((nkt * 9 + nks) * MFT) * 32;
                    nh0 = p[0]; nh1 = p[32];
                } else {
                    nh0 = nh1 = make_uint4(0u, 0u, 0u, 0u);
                }
            }

            const int dy = ks / 3, dx = ks % 3;   // compile-time after unroll
            const uint32_t* b0p = rb + (t * 3 + dy) * SR + dx + 3 + g;
            const uint32_t* b1p = b0p + 12 * SR;   // pair t+4

#pragma unroll
            for (int nf = 0; nf < 8; nf += 2) {
                uint32_t bA0 = b0p[nf * 8],     bA1 = b1p[nf * 8];
                uint32_t bB0 = b0p[nf * 8 + 8], bB1 = b1p[nf * 8 + 8];
                MMA_F16(acc[0][nf],     ah0.x, ah0.y, ah0.z, ah0.w, bA0, bA1);
                MMA_F16(acc[1][nf],     ah1.x, ah1.y, ah1.z, ah1.w, bA0, bA1);
                MMA_F16(acc[0][nf + 1], ah0.x, ah0.y, ah0.z, ah0.w, bB0, bB1);
                MMA_F16(acc[1][nf + 1], ah1.x, ah1.y, ah1.z, ah1.w, bB0, bB1);
            }
            ah0 = nh0; ah1 = nh1;
        }
        __syncthreads();
    }

    // ---- epilogue: bias + leaky; write fp32 feat + fp16 pair shadow ----
    const int q = lane & 3, g2 = lane >> 2;
    float* outB = outBase + (size_t)b * FEAT_STRIDE;
    __half* outH = (__half*)(outPairBase + (size_t)b * HALF_B);
#pragma unroll
    for (int mi = 0; mi < 2; mi++) {
        int m0 = wm0 + mi * 16 + g2;
        float bLo = __ldg(bias + m0), bHi = __ldg(bias + m0 + 8);
        float* o0 = outB + (size_t)m0 * HW;
        float* o1 = o0 + 8 * HW;
        size_t hb0 = ((size_t)(m0 >> 1) * HW) * 2 + (m0 & 1);
        size_t hb1 = ((size_t)((m0 + 8) >> 1) * HW) * 2 + (m0 & 1);
#pragma unroll
        for (int nf = 0; nf < 8; nf++) {
            int off = y * W + x0 + nf * 8 + 2 * q;
            float v0 = acc[mi][nf][0] + bLo, v1 = acc[mi][nf][1] + bLo;
            float v2 = acc[mi][nf][2] + bHi, v3 = acc[mi][nf][3] + bHi;
            v0 = (v0 >= 0.f) ? v0 : 0.1f * v0;
            v1 = (v1 >= 0.f) ? v1 : 0.1f * v1;
            v2 = (v2 >= 0.f) ? v2 : 0.1f * v2;
            v3 = (v3 >= 0.f) ? v3 : 0.1f * v3;
            *(float2*)(o0 + off) = make_float2(v0, v1);
            *(float2*)(o1 + off) = make_float2(v2, v3);
            outH[hb0 + (size_t)off * 2]       = __float2half_rn(v0);
            outH[hb0 + (size_t)(off + 1) * 2] = __float2half_rn(v1);
            outH[hb1 + (size_t)off * 2]       = __float2half_rn(v2);
            outH[hb1 + (size_t)(off + 1) * 2] = __float2half_rn(v3);
        }
    }
}

// ---------------------------------------------------------------------------
// Launch
// ---------------------------------------------------------------------------
extern "C" void kernel_launch(void* const* d_in, const int* in_sizes, int n_in,
                              void* d_out, int out_size)
{
    (void)in_sizes; (void)n_in; (void)out_size;
    const float* tenOne    = (const float*)d_in[0];
    const float* tenTwo    = (const float*)d_in[1];
    const float* prev_flow = (const float*)d_in[2];
    const float* prev_feat = (const float*)d_in[3];
    const float* w_upflow  = (const float*)d_in[4];
    const float* b_upflow  = (const float*)d_in[5];
    const float* w_upfeat  = (const float*)d_in[6];
    const float* b_upfeat  = (const float*)d_in[7];
    const float* w1 = (const float*)d_in[8];   const float* b1 = (const float*)d_in[9];
    const float* w2 = (const float*)d_in[10];  const float* b2 = (const float*)d_in[11];
    const float* w3 = (const float*)d_in[12];  const float* b3 = (const float*)d_in[13];
    const float* w4 = (const float*)d_in[14];  const float* b4 = (const float*)d_in[15];
    const float* w5 = (const float*)d_in[16];  const float* b5 = (const float*)d_in[17];
    const float* w6 = (const float*)d_in[18];  const float* b6 = (const float*)d_in[19];

    float* flow = (float*)d_out;
    float* feat = flow + (size_t)Bn * 2 * HW;

    uint32_t* apack;
    cudaGetSymbolAddress((void**)&apack, g_Apack);
    uint32_t* halfu;
    cudaGetSymbolAddress((void**)&halfu, g_half);
    float* upw;
    cudaGetSymbolAddress((void**)&upw, g_upw);

    const int NPIX = Bn * HW;

    // 0. weight pre-packs
    pack_all_kernel<<<(APACK_TOTAL + 255) / 256, 256>>>(w1, w2, w3, w4, w5, apack);
    pack_upw_kernel<<<(4 * 663 * 8 + 255) / 256, 256>>>(w_upflow, w_upfeat, upw);
    // 1. both upconvs
    upconv_both_kernel<<<dim3((NPIX + 255) / 256, 2), 256>>>(
        prev_flow, b_upflow, prev_feat, b_upfeat, feat);
    // 2. tenOne
    {
        size_t n4 = (size_t)Bn * C1CH * HW / 4;
        copy_t1_kernel<<<(unsigned)((n4 + 255) / 256), 256>>>(tenOne, feat);
    }
    // 3. warp tenTwo
    warp_kernel<<<(NPIX + 255) / 256, 256>>>(tenTwo, feat);
    // 4. correlation
    corr_kernel<<<dim3(W / 32, H / 4, Bn), 128>>>(tenOne, feat);

    // 5-9. fp16 mma conv tower (pair-interleaved)
    conv_mma5_kernel<181, 128, 128, 4><<<dim3(128, Bn), 128>>>(
        halfu + (size_t)(OFF_VOL / 2) * HW, (const uint4*)(apack + APACK_OFF1), b1,
        feat + (size_t)OFF_C1 * HW, halfu + (size_t)(OFF_C1 / 2) * HW);
    conv_mma5_kernel<309, 128, 128, 4><<<dim3(128, Bn), 128>>>(
        halfu + (size_t)(OFF_C1 / 2) * HW, (const uint4*)(apack + APACK_OFF2), b2,
        feat + (size_t)OFF_C2 * HW, halfu + (size_t)(OFF_C2 / 2) * HW);
    conv_mma5_kernel<437, 96, 96, 5><<<dim3(128, Bn), 96>>>(
        halfu + (size_t)(OFF_C2 / 2) * HW, (const uint4*)(apack + APACK_OFF3), b3,
        feat + (size_t)OFF_C3 * HW, halfu + (size_t)(OFF_C3 / 2) * HW);
    conv_mma5_kernel<533, 64, 64, 8><<<dim3(128, Bn), 64>>>(
        halfu + (size_t)(OFF_C3 / 2) * HW, (const uint4*)(apack + APACK_OFF4), b4,
        feat + (size_t)OFF_C4 * HW, halfu + (size_t)(OFF_C4 / 2) * HW);
    conv_mma5_kernel<597, 32, 32, 12><<<dim3(128, Bn), 32>>>(
        halfu + (size_t)(OFF_C4 / 2) * HW, (const uint4*)(apack + APACK_OFF5), b5,
        feat + (size_t)OFF_C5 * HW, halfu + (size_t)(OFF_C5 / 2) * HW);

    // 10. conv6 (Cout=2) -> flow, FFMA path
    conv3x3_kernel<2><<<dim3(1, 8, Bn), 256>>>(
        feat + (size_t)OFF_C5 * HW, w6, b6, flow,
        629, FEAT_STRIDE, 2 * HW);
}

// round 15
// speedup vs baseline: 2.0487x; 1.0017x over previous
#include <cuda_runtime.h>
#include <cuda_fp16.h>
#include <math.h>
#include <stdint.h>

// ---------------------------------------------------------------------------
#define Bn 8
#define H 64
#define W 128
#define HW (H * W)
#define C1CH 96
#define HIN 32
#define WIN 64
#define HWIN (HIN * WIN)
#define PREVC 661

#define FEAT_C 629
#define FEAT_STRIDE (FEAT_C * HW)

// [c5(32) | c4(64) | c3(96) | c2(128) | c1(128) | vol(81) | tenOne(96) | flow(2) | upfeat(2)]
#define OFF_C5   0
#define OFF_C4   32
#define OFF_C3   96
#define OFF_C2   192
#define OFF_C1   320
#define OFF_VOL  448
#define OFF_T1   529
#define OFF_FLOW 625
#define OFF_UPF  627

#define NQG 40                         // 640-channel padded space / 16

__device__ float g_warped[(size_t)Bn * C1CH * HW];

// quad-interleaved fp16 shadow: per (b, g16, pix): 4 u64 slots,
// slot s = {half2(ch 16g+2s, +1), half2(ch 16g+8+2s, +1)}.
// Channels 629..639 are padding and stay zero (device globals zero-init,
// writers never touch them).
__device__ unsigned long long g_halfq[(size_t)Bn * NQG * HW * 4];

// fp16 A-fragments, chunk = 144 k; k-order: tap-major (ks=tap), channel-minor
#define APACK_OFF1 0
#define APACK_OFF2 110592      // + 12*9*8*128
#define APACK_OFF3 294912      // + 20*9*8*128
#define APACK_OFF4 488448      // + 28*9*6*128
#define APACK_OFF5 645120      // + 34*9*4*128
#define APACK_TOTAL 732672     // + 38*9*2*128
__device__ uint32_t g_Apack[APACK_TOTAL];

// per-parity packed upconv weights: [parity 4][ci 663][8 floats]
__device__ float g_upw[4 * 663 * 8];

// ---------------------------------------------------------------------------
__device__ __forceinline__ uint32_t smem_u32(const void* p) {
    uint32_t a;
    asm("{ .reg .u64 t; cvta.to.shared.u64 t, %1; cvt.u32.u64 %0, t; }" : "=r"(a) : "l"(p));
    return a;
}
__device__ __forceinline__ void cp_async16(uint32_t dst, const void* src) {
    asm volatile("cp.async.ca.shared.global [%0], [%1], 16;" :: "r"(dst), "l"(src));
}
#define CP_COMMIT() asm volatile("cp.async.commit_group;")
#define CP_WAIT0()  asm volatile("cp.async.wait_group 0;")
#define CP_WAIT1()  asm volatile("cp.async.wait_group 1;")

// scalar write into the quad-interleaved shadow
__device__ __forceinline__ void st_half(int b, int ch, int pix, float v) {
    int g16 = ch >> 4, r = ch & 15;
    int pos = 4 * ((r & 7) >> 1) + ((r >> 3) << 1) + (r & 1);
    __half* hp = (__half*)g_halfq + (((size_t)b * NQG + g16) * HW + pix) * 16 + pos;
    *hp = __float2half_rn(v);
}

#define MMA_F16(c, a0, a1, a2, a3, b0v, b1v) \
    asm volatile( \
        "mma.sync.aligned.m16n8k16.row.col.f32.f16.f16.f32 " \
        "{%0,%1,%2,%3}, {%4,%5,%6,%7}, {%8,%9}, {%0,%1,%2,%3};" \
        : "+f"((c)[0]), "+f"((c)[1]), "+f"((c)[2]), "+f"((c)[3]) \
        : "r"(a0), "r"(a1), "r"(a2), "r"(a3), \
          "r"(b0v), "r"(b1v))

// ---------------------------------------------------------------------------
// Weight pre-pack: k-order tap-major.  u32 idx = (((kt*9+ks)*MFT+mf)*32+lane)*4+reg
//   m  = mf*16 + (lane>>2) + 8*(reg&1)
//   ch = kt*16 + (lane&3)*2 + 8*(reg>>1) + {0,1};  tap = ks
// ---------------------------------------------------------------------------
__device__ __forceinline__ void pack_one(const float* w, uint32_t* dst, int idx,
                                         int Cin, int Cout)
{
    int MFT = Cout >> 4;
    int reg = idx & 3, lane = (idx >> 2) & 31;
    int u = idx >> 7;
    int mf = u % MFT;
    int v3 = u / MFT;
    int ks = v3 % 9, kt = v3 / 9;
    int m = mf * 16 + (lane >> 2) + 8 * (reg & 1);
    int ch = kt * 16 + (lane & 3) * 2 + 8 * (reg >> 1);
    float v0 = (ch     < Cin) ? w[((size_t)m * Cin + ch)     * 9 + ks] : 0.f;
    float v1 = (ch + 1 < Cin) ? w[((size_t)m * Cin + ch + 1) * 9 + ks] : 0.f;
    __half h0 = __float2half_rn(v0), h1 = __float2half_rn(v1);
    dst[idx] = (uint32_t)__half_as_ushort(h0) | ((uint32_t)__half_as_ushort(h1) << 16);
}

__global__ void pack_all_kernel(const float* __restrict__ w1, const float* __restrict__ w2,
                                const float* __restrict__ w3, const float* __restrict__ w4,
                                const float* __restrict__ w5, uint32_t* __restrict__ dst)
{
    int idx = blockIdx.x * blockDim.x + threadIdx.x;
    if (idx >= APACK_TOTAL) return;
    if      (idx < APACK_OFF2) pack_one(w1, dst + APACK_OFF1, idx - APACK_OFF1, 181, 128);
    else if (idx < APACK_OFF3) pack_one(w2, dst + APACK_OFF2, idx - APACK_OFF2, 309, 128);
    else if (idx < APACK_OFF4) pack_one(w3, dst + APACK_OFF3, idx - APACK_OFF3, 437, 96);
    else if (idx < APACK_OFF5) pack_one(w4, dst + APACK_OFF4, idx - APACK_OFF4, 533, 64);
    else                       pack_one(w5, dst + APACK_OFF5, idx - APACK_OFF5, 597, 32);
}

// per-parity upconv weight pack
__global__ void pack_upw_kernel(const float* __restrict__ wF, const float* __restrict__ wU,
                                float* __restrict__ dst)
{
    int idx = blockIdx.x * blockDim.x + threadIdx.x;
    if (idx >= 4 * 663 * 8) return;
    int j = idx & 7;
    int q = idx >> 3;
    int ci_all = q % 663, parity = q / 663;
    int py = parity >> 1, px = parity & 1;
    int ky0 = 1 + py, ky1 = py ? 0 : 3;
    int kx0 = 1 + px, kx1 = px ? 0 : 3;
    int cout = j >> 2, tp = j & 3;
    int ky = (tp < 2) ? ky0 : ky1;
    int kx = (tp & 1) ? kx1 : kx0;
    const float* src;
    int ci;
    if (ci_all < 2) { src = wF; ci = ci_all; }
    else            { src = wU; ci = ci_all - 2; }
    dst[idx] = src[(size_t)ci * 32 + cout * 16 + ky * 4 + kx];
}

// ---------------------------------------------------------------------------
// Merged ConvTranspose2d(k=4,s=2,p=1), Cout=2, packed parity weights.
// ---------------------------------------------------------------------------
__global__ void upconv_both_kernel(const float* __restrict__ inF,
                                   const float* __restrict__ bF,
                                   const float* __restrict__ inU,
                                   const float* __restrict__ bU,
                                   float* __restrict__ feat)
{
    int gid = blockIdx.x * blockDim.x + threadIdx.x;
    if (gid >= Bn * HW) return;
    const int which = blockIdx.y;
    const float* in  = which ? inU : inF;
    const float* bias= which ? bU  : bF;
    const int Cin    = which ? PREVC : 2;
    const int choff  = which ? OFF_UPF : OFF_FLOW;

    int b = gid / HW;
    int pix = gid - b * HW;
    int y = pix / W, x = pix - (pix / W) * W;

    int iy0 = y >> 1;
    int iy1 = (y >> 1) + ((y & 1) ? 1 : -1);
    int ix0 = x >> 1;
    int ix1 = (x >> 1) + ((x & 1) ? 1 : -1);
    bool vy1 = (unsigned)iy1 < HIN;
    bool vx1 = (unsigned)ix1 < WIN;

    int parity = (y & 1) * 2 + (x & 1);
    const float* wbase = g_upw + (size_t)parity * (663 * 8) + (which ? 16 : 0);

    float a0 = bias[0], a1 = bias[1];
    const float* pin = in + (size_t)b * Cin * HWIN;
    int p00 = iy0 * WIN + ix0, p01 = iy0 * WIN + ix1;
    int p10 = iy1 * WIN + ix0, p11 = iy1 * WIN + ix1;

    for (int ci = 0; ci < Cin; ci++) {
        const float* p = pin + (size_t)ci * HWIN;
        float4 f0 = *(const float4*)(wbase + (size_t)ci * 8);
        float4 f1 = *(const float4*)(wbase + (size_t)ci * 8 + 4);
        float u0 = p[p00];
        float u1 = vx1 ? p[p01] : 0.f;
        float u2 = vy1 ? p[p10] : 0.f;
        float u3 = (vy1 && vx1) ? p[p11] : 0.f;
        a0 += u0 * f0.x + u1 * f0.y + u2 * f0.z + u3 * f0.w;
        a1 += u0 * f1.x + u1 * f1.y + u2 * f1.z + u3 * f1.w;
    }
    size_t o = (size_t)b * FEAT_STRIDE + (size_t)choff * HW + pix;
    feat[o]      = a0;
    feat[o + HW] = a1;
    st_half(b, choff,     pix, a0);
    st_half(b, choff + 1, pix, a1);
}

__global__ void copy_t1_kernel(const float* __restrict__ t1, float* __restrict__ feat)
{
    size_t i = (size_t)blockIdx.x * blockDim.x + threadIdx.x;
    const size_t n4 = (size_t)Bn * C1CH * HW / 4;
    if (i >= n4) return;
    const size_t per = (size_t)C1CH * HW / 4;
    size_t b = i / per, r = i - b * per;
    int ch = OFF_T1 + (int)(r / (HW / 4));
    int pix = (int)(r % (HW / 4)) * 4;
    float4 v = ((const float4*)t1)[i];
    size_t o = b * (size_t)FEAT_STRIDE + (size_t)OFF_T1 * HW;
    ((float4*)(feat + o))[r] = v;
    st_half((int)b, ch, pix,     v.x);
    st_half((int)b, ch, pix + 1, v.y);
    st_half((int)b, ch, pix + 2, v.z);
    st_half((int)b, ch, pix + 3, v.w);
}

__global__ void warp_kernel(const float* __restrict__ tenTwo, const float* __restrict__ feat)
{
    int gid = blockIdx.x * blockDim.x + threadIdx.x;
    if (gid >= Bn * HW) return;
    int b = gid / HW;
    int pix = gid - b * HW;
    int y = pix / W, x = pix - (pix / W) * W;

    const float* fl = feat + (size_t)b * FEAT_STRIDE + (size_t)OFF_FLOW * HW + pix;
    float px = (float)x + fl[0]  * 1.25f;
    float py = (float)y + fl[HW] * 1.25f;
    float fx = floorf(px), fy = floorf(py);
    float wx = px - fx, wy = py - fy;
    int ix0 = (int)fx, iy0 = (int)fy;
    int ix1 = ix0 + 1, iy1 = iy0 + 1;
    bool vx0 = (unsigned)ix0 < W, vx1 = (unsigned)ix1 < W;
    bool vy0 = (unsigned)iy0 < H, vy1 = (unsigned)iy1 < H;
    float w00 = (1.f - wy) * (1.f - wx), w01 = (1.f - wy) * wx;
    float w10 = wy * (1.f - wx),         w11 = wy * wx;
    int o00 = iy0 * W + ix0, o01 = iy0 * W + ix1;
    int o10 = iy1 * W + ix0, o11 = iy1 * W + ix1;

    const float* t = tenTwo + (size_t)b * C1CH * HW;
    float* o = g_warped + (size_t)b * C1CH * HW + pix;
    for (int c = 0; c < C1CH; c++) {
        const float* tc = t + (size_t)c * HW;
        float v = 0.f;
        if (vy0 && vx0) v += tc[o00] * w00;
        if (vy0 && vx1) v += tc[o01] * w01;
        if (vy1 && vx0) v += tc[o10] * w10;
        if (vy1 && vx1) v += tc[o11] * w11;
        o[(size_t)c * HW] = v;
    }
}

__global__ __launch_bounds__(128) void corr_kernel(const float* __restrict__ tenOne,
                                                   float* __restrict__ feat)
{
    __shared__ float s_f1[4][32];
    __shared__ float s_w2[12][40];
    int tid = threadIdx.x;
    int tx = tid & 31, ty = tid >> 5;
    int x0 = blockIdx.x * 32, y0 = blockIdx.y * 4, b = blockIdx.z;

    float acc[81];
#pragma unroll
    for (int d = 0; d < 81; d++) acc[d] = 0.f;

    const float* f1 = tenOne + (size_t)b * C1CH * HW;
    const float* f2 = g_warped + (size_t)b * C1CH * HW;

    for (int c = 0; c < C1CH; c++) {
        const float* f1c = f1 + (size_t)c * HW;
        const float* f2c = f2 + (size_t)c * HW;
        __syncthreads();
        s_f1[ty][tx] = f1c[(y0 + ty) * W + x0 + tx];
#pragma unroll
        for (int i = 0; i < 4; i++) {
            int idx = tid + i * 128;
            if (idx < 480) {
                int r = idx / 40, cc = idx - (idx / 40) * 40;
                int gy = y0 - 4 + r, gx = x0 - 4 + cc;
                float v = 0.f;
                if ((unsigned)gy < H && (unsigned)gx < W) v = f2c[gy * W + gx];
                s_w2[r][cc] = v;
            }
        }
        __syncthreads();
        float a = s_f1[ty][tx];
#pragma unroll
        for (int dy = 0; dy < 9; dy++)
#pragma unroll
            for (int dx = 0; dx < 9; dx++)
                acc[dy * 9 + dx] += a * s_w2[ty + dy][tx + dx];
    }

    int pix = (y0 + ty) * W + x0 + tx;
    size_t obase = (size_t)b * FEAT_STRIDE + (size_t)OFF_VOL * HW + pix;
    const float inv = 1.f / 96.f;
#pragma unroll
    for (int d = 0; d < 81; d++) {
        float v = acc[d] * inv;
        v = (v >= 0.f) ? v : 0.1f * v;
        feat[obase + (size_t)d * HW] = v;
        st_half(b, OFF_VOL + d, pix, v);
    }
}

// ---------------------------------------------------------------------------
// FFMA direct 3x3 conv (conv6, Cout=2)
// ---------------------------------------------------------------------------
template <int COUT_BLK>
__global__ __launch_bounds__(256) void conv3x3_kernel(
    const float* __restrict__ in, const float* __restrict__ w,
    const float* __restrict__ bias, float* __restrict__ out,
    int Cin, int inStride, int outStride)
{
    __shared__ float s_in[18][66];
    __shared__ float s_w[COUT_BLK * 9];
    const int tid = threadIdx.x;
    const int tx = tid & 15, ty = tid >> 4;
    const int g = blockIdx.x;
    const int tileX = blockIdx.y & 1, tileY = blockIdx.y >> 1;
    const int b = blockIdx.z;
    const int x0 = tileX * 64, y0 = tileY * 16;

    const float* inB = in + (size_t)b * inStride;
    float acc[COUT_BLK][4];
#pragma unroll
    for (int c = 0; c < COUT_BLK; c++)
#pragma unroll
        for (int p = 0; p < 4; p++) acc[c][p] = 0.f;

    for (int ci = 0; ci < Cin; ci++) {
        const float* ch = inB + (size_t)ci * HW;
#pragma unroll
        for (int i = 0; i < 5; i++) {
            int idx = tid + i * 256;
            if (idx < 18 * 66) {
                int r = idx / 66, c = idx - (idx / 66) * 66;
                int gy = y0 - 1 + r, gx = x0 - 1 + c;
                float v = 0.f;
                if ((unsigned)gy < H && (unsigned)gx < W) v = ch[gy * W + gx];
                s_in[r][c] = v;
            }
        }
        if (tid < COUT_BLK * 9)
            s_w[tid] = w[((size_t)(g * COUT_BLK + tid / 9) * Cin + ci) * 9 + tid % 9];
        __syncthreads();

        float r0[6], r1[6], r2[6];
#pragma unroll
        for (int k = 0; k < 6; k++) {
            r0[k] = s_in[ty][tx * 4 + k];
            r1[k] = s_in[ty + 1][tx * 4 + k];
            r2[k] = s_in[ty + 2][tx * 4 + k];
        }
#pragma unroll
        for (int co = 0; co < COUT_BLK; co++) {
            float w0 = s_w[co * 9 + 0], w1v = s_w[co * 9 + 1], w2v = s_w[co * 9 + 2];
            float w3v = s_w[co * 9 + 3], w4v = s_w[co * 9 + 4], w5v = s_w[co * 9 + 5];
            float w6v = s_w[co * 9 + 6], w7v = s_w[co * 9 + 7], w8v = s_w[co * 9 + 8];
#pragma unroll
            for (int p = 0; p < 4; p++) {
                float s = acc[co][p];
                s += w0  * r0[p]; s += w1v * r0[p + 1]; s += w2v * r0[p + 2];
                s += w3v * r1[p]; s += w4v * r1[p + 1]; s += w5v * r1[p + 2];
                s += w6v * r2[p]; s += w7v * r2[p + 1]; s += w8v * r2[p + 2];
                acc[co][p] = s;
            }
        }
        __syncthreads();
    }

#pragma unroll
    for (int co = 0; co < COUT_BLK; co++) {
        float bi = bias[g * COUT_BLK + co];
        float* o = out + (size_t)b * outStride + (size_t)(g * COUT_BLK + co) * HW
                 + (y0 + ty) * W + x0 + tx * 4;
#pragma unroll
        for (int p = 0; p < 4; p++) {
            float v = acc[co][p] + bi;
            o[p] = (v >= 0.f) ? v : 0.1f * v;
        }
    }
}

// ---------------------------------------------------------------------------
// conv_mma6: N=64 tiles, quad-interleaved B -> one LDS.64 per b-fragment,
// zero perms, no channel predicates in staging (padded zeroed channel space).
// ---------------------------------------------------------------------------
#define SRQ 268                 // u64 per staged row
#define BUFQ (3 * SRQ)          // 804 u64 per buffer

template <int Cin, int Cout, int THREADS, int MINB>
__global__ __launch_bounds__(THREADS, MINB) void conv_mma6_kernel(
    int base16,                               // input channel base / 16
    const uint4* __restrict__ Apack,
    const float* __restrict__ bias,
    float* __restrict__ outBase,              // feat + outOff*HW (b=0)
    int outOff)                               // output channel base (mult of 16)
{
    constexpr int nC  = (Cin + 15) / 16;
    constexpr int MFT = Cout / 16;

    __shared__ unsigned long long rawq[2 * BUFQ];
    const int tid = threadIdx.x, lane = tid & 31, wrp = tid >> 5;
    const int wm0 = wrp * 32;
    const int y  = blockIdx.x >> 1;
    const int x0 = (blockIdx.x & 1) << 6;
    const int b  = blockIdx.y;
    const unsigned long long* inQ = g_halfq + (size_t)b * NQG * HW * 4;
    const uint32_t rawAddr = smem_u32(rawq);
    const uint4* apw = Apack + (size_t)(wrp * 2) * 32 + lane;

    float acc[2][8][4];
#pragma unroll
    for (int mi = 0; mi < 2; mi++)
#pragma unroll
        for (int nf = 0; nf < 8; nf++)
#pragma unroll
            for (int p = 0; p < 4; p++) acc[mi][nf][p] = 0.f;

    auto stage = [&](int kt, int bufsel) {
        const unsigned long long* src = inQ + (size_t)(base16 + kt) * HW * 4;
        // interior: 3 rows x 64 px x 2 halves (16B each)
        for (int i = tid; i < 384; i += THREADS) {
            int r = i >> 7, j = i & 127;
            int p = j >> 1, hs = j & 1;
            int yr = y + r - 1;
            uint32_t didx = (uint32_t)(bufsel * BUFQ + r * SRQ + (1 + p) * 4 + hs * 2);
            if ((unsigned)yr < (unsigned)H)
                cp_async16(rawAddr + didx * 8, src + ((size_t)yr * W + x0 + p) * 4 + hs * 2);
            else
                *(uint4*)(rawq + didx) = make_uint4(0u, 0u, 0u, 0u);
        }
        // edges: 3 rows x 2 sides x 2 halves
        for (int e = tid; e < 12; e += THREADS) {
            int r = e >> 2, j = e & 3;
            int side = j >> 1, hs = j & 1;
            int yr = y + r - 1;
            int x = side ? (x0 + 64) : (x0 - 1);
            uint32_t didx = (uint32_t)(bufsel * BUFQ + r * SRQ + (side ? 260 : 0) + hs * 2);
            if ((unsigned)yr < (unsigned)H && (unsigned)x < (unsigned)W)
                cp_async16(rawAddr + didx * 8, src + ((size_t)yr * W + x) * 4 + hs * 2);
            else
                *(uint4*)(rawq + didx) = make_uint4(0u, 0u, 0u, 0u);
        }
    };

    stage(0, 0);
    CP_COMMIT();

    const int t = lane & 3;
    const int g = lane >> 2;

    uint4 ah0, ah1;
    { const uint4* p = apw; ah0 = p[0]; ah1 = p[32]; }

    for (int kt = 0; kt < nC; kt++) {
        const int buf = kt & 1;
        if (kt + 1 < nC) {
            stage(kt + 1, buf ^ 1);
            CP_COMMIT();
            CP_WAIT1();
        } else {
            CP_WAIT0();
        }
        __syncthreads();

        const unsigned long long* rbq = rawq + buf * BUFQ;

#pragma unroll
        for (int ks = 0; ks < 9; ks++) {
            uint4 nh0, nh1;
            {
                int nkt = kt, nks = ks + 1;
                if (nks == 9) { nkt = kt + 1; nks = 0; }
                if (nkt < nC) {
                    const uint4* p = apw + (size_t)((nkt * 9 + nks) * MFT) * 32;
                    nh0 = p[0]; nh1 = p[32];
                } else {
                    nh0 = nh1 = make_uint4(0u, 0u, 0u, 0u);
                }
            }

            const int dy = ks / 3, dx = ks % 3;   // compile-time after unroll
            const unsigned long long* bp = rbq + dy * SRQ + (g + dx) * 4 + t;

#pragma unroll
            for (int nf = 0; nf < 8; nf += 2) {
                unsigned long long vA = bp[nf * 32];
                unsigned long long vB = bp[nf * 32 + 32];
                uint32_t bA0 = (uint32_t)vA, bA1 = (uint32_t)(vA >> 32);
                uint32_t bB0 = (uint32_t)vB, bB1 = (uint32_t)(vB >> 32);
                MMA_F16(acc[0][nf],     ah0.x, ah0.y, ah0.z, ah0.w, bA0, bA1);
                MMA_F16(acc[1][nf],     ah1.x, ah1.y, ah1.z, ah1.w, bA0, bA1);
                MMA_F16(acc[0][nf + 1], ah0.x, ah0.y, ah0.z, ah0.w, bB0, bB1);
                MMA_F16(acc[1][nf + 1], ah1.x, ah1.y, ah1.z, ah1.w, bB0, bB1);
            }
            ah0 = nh0; ah1 = nh1;
        }
        __syncthreads();
    }

    // ---- epilogue: bias + leaky; write fp32 feat + quad fp16 shadow ----
    const int q = lane & 3, g2 = lane >> 2;
    float* outB = outBase + (size_t)b * FEAT_STRIDE;
    __half* hq = (__half*)g_halfq + ((size_t)b * NQG) * HW * 16;
#pragma unroll
    for (int mi = 0; mi < 2; mi++) {
        int m0 = wm0 + mi * 16 + g2;
        int am = outOff + m0;                 // (am & 15) < 8 always
        float bLo = __ldg(bias + m0), bHi = __ldg(bias + m0 + 8);
        float* o0 = outB + (size_t)m0 * HW;
        float* o1 = o0 + 8 * HW;
        size_t hb = (size_t)(am >> 4) * HW * 16 + 4 * ((am & 15) >> 1) + (am & 1);
#pragma unroll
        for (int nf = 0; nf < 8; nf++) {
            int off = y * W + x0 + nf * 8 + 2 * q;
            float v0 = acc[mi][nf][0] + bLo, v1 = acc[mi][nf][1] + bLo;
            float v2 = acc[mi][nf][2] + bHi, v3 = acc[mi][nf][3] + bHi;
            v0 = (v0 >= 0.f) ? v0 : 0.1f * v0;
            v1 = (v1 >= 0.f) ? v1 : 0.1f * v1;
            v2 = (v2 >= 0.f) ? v2 : 0.1f * v2;
            v3 = (v3 >= 0.f) ? v3 : 0.1f * v3;
            *(float2*)(o0 + off) = make_float2(v0, v1);
            *(float2*)(o1 + off) = make_float2(v2, v3);
            size_t h = hb + (size_t)off * 16;
            hq[h]          = __float2half_rn(v0);
            hq[h + 2]      = __float2half_rn(v2);
            hq[h + 16]     = __float2half_rn(v1);
            hq[h + 18]     = __float2half_rn(v3);
        }
    }
}

// ---------------------------------------------------------------------------
// Launch
// ---------------------------------------------------------------------------
extern "C" void kernel_launch(void* const* d_in, const int* in_sizes, int n_in,
                              void* d_out, int out_size)
{
    (void)in_sizes; (void)n_in; (void)out_size;
    const float* tenOne    = (const float*)d_in[0];
    const float* tenTwo    = (const float*)d_in[1];
    const float* prev_flow = (const float*)d_in[2];
    const float* prev_feat = (const float*)d_in[3];
    const float* w_upflow  = (const float*)d_in[4];
    const float* b_upflow  = (const float*)d_in[5];
    const float* w_upfeat  = (const float*)d_in[6];
    const float* b_upfeat  = (const float*)d_in[7];
    const float* w1 = (const float*)d_in[8];   const float* b1 = (const float*)d_in[9];
    const float* w2 = (const float*)d_in[10];  const float* b2 = (const float*)d_in[11];
    const float* w3 = (const float*)d_in[12];  const float* b3 = (const float*)d_in[13];
    const float* w4 = (const float*)d_in[14];  const float* b4 = (const float*)d_in[15];
    const float* w5 = (const float*)d_in[16];  const float* b5 = (const float*)d_in[17];
    const float* w6 = (const float*)d_in[18];  const float* b6 = (const float*)d_in[19];

    float* flow = (float*)d_out;
    float* feat = flow + (size_t)Bn * 2 * HW;

    uint32_t* apack;
    cudaGetSymbolAddress((void**)&apack, g_Apack);
    float* upw;
    cudaGetSymbolAddress((void**)&upw, g_upw);

    const int NPIX = Bn * HW;

    // 0. weight pre-packs
    pack_all_kernel<<<(APACK_TOTAL + 255) / 256, 256>>>(w1, w2, w3, w4, w5, apack);
    pack_upw_kernel<<<(4 * 663 * 8 + 255) / 256, 256>>>(w_upflow, w_upfeat, upw);
    // 1. both upconvs
    upconv_both_kernel<<<dim3((NPIX + 255) / 256, 2), 256>>>(
        prev_flow, b_upflow, prev_feat, b_upfeat, feat);
    // 2. tenOne
    {
        size_t n4 = (size_t)Bn * C1CH * HW / 4;
        copy_t1_kernel<<<(unsigned)((n4 + 255) / 256), 256>>>(tenOne, feat);
    }
    // 3. warp tenTwo
    warp_kernel<<<(NPIX + 255) / 256, 256>>>(tenTwo, feat);
    // 4. correlation
    corr_kernel<<<dim3(W / 32, H / 4, Bn), 128>>>(tenOne, feat);

    // 5-9. fp16 mma conv tower (quad-interleaved)
    conv_mma6_kernel<181, 128, 128, 4><<<dim3(128, Bn), 128>>>(
        OFF_VOL / 16, (const uint4*)(apack + APACK_OFF1), b1,
        feat + (size_t)OFF_C1 * HW, OFF_C1);
    conv_mma6_kernel<309, 128, 128, 4><<<dim3(128, Bn), 128>>>(
        OFF_C1 / 16, (const uint4*)(apack + APACK_OFF2), b2,
        feat + (size_t)OFF_C2 * HW, OFF_C2);
    conv_mma6_kernel<437, 96, 96, 5><<<dim3(128, Bn), 96>>>(
        OFF_C2 / 16, (const uint4*)(apack + APACK_OFF3), b3,
        feat + (size_t)OFF_C3 * HW, OFF_C3);
    conv_mma6_kernel<533, 64, 64, 8><<<dim3(128, Bn), 64>>>(
        OFF_C3 / 16, (const uint4*)(apack + APACK_OFF4), b4,
        feat + (size_t)OFF_C4 * HW, OFF_C4);
    conv_mma6_kernel<597, 32, 32, 12><<<dim3(128, Bn), 32>>>(
        OFF_C4 / 16, (const uint4*)(apack + APACK_OFF5), b5,
        feat + (size_t)OFF_C5 * HW, OFF_C5);

    // 10. conv6 (Cout=2) -> flow, FFMA path
    conv3x3_kernel<2><<<dim3(1, 8, Bn), 256>>>(
        feat + (size_t)OFF_C5 * HW, w6, b6, flow,
        629, FEAT_STRIDE, 2 * HW);
}